// round 1
// baseline (speedup 1.0000x reference)
#include <cuda_runtime.h>

#define T_FRAMES 2048
#define D_HID    1024
#define V_VOC    28

// Scratch (no allocation allowed -> device globals)
__device__ float g_U[T_FRAMES * V_VOC];   // U[t][v] = Uo[v] . x[t-1], U[0][*] = 0
__device__ float g_S[D_HID];              // colsum of x over t
__device__ float g_CO[V_VOC];             // Co @ g_S

// ---------------------------------------------------------------------------
// Kernel A: U[t+1][v] = Uo[v] . x[t]   (28 x 1024 x 2048 GEMM)
// 256 blocks x 128 threads, each block handles 8 consecutive t rows.
// ---------------------------------------------------------------------------
__global__ void __launch_bounds__(128) kA_computeU(const float* __restrict__ x,
                                                   const float* __restrict__ Uo) {
    __shared__ float xs[8][D_HID];                 // 32 KB
    const int t0 = blockIdx.x * 8;

    // cooperative vectorized load of 8 x-rows
    const float4* xv = reinterpret_cast<const float4*>(x + (size_t)t0 * D_HID);
    float4* sv = reinterpret_cast<float4*>(&xs[0][0]);
    #pragma unroll
    for (int i = threadIdx.x; i < 8 * D_HID / 4; i += 128)
        sv[i] = xv[i];
    __syncthreads();

    const int warp = threadIdx.x >> 5;
    const int lane = threadIdx.x & 31;

    #pragma unroll
    for (int vi = 0; vi < 7; vi++) {
        const int v = warp * 7 + vi;               // 4 warps * 7 = 28 outputs
        const float* uoRow = Uo + v * D_HID;
        float acc[8];
        #pragma unroll
        for (int r = 0; r < 8; r++) acc[r] = 0.f;

        #pragma unroll 4
        for (int j = 0; j < 32; j++) {
            const int d = j * 32 + lane;
            const float uo = __ldg(&uoRow[d]);
            #pragma unroll
            for (int r = 0; r < 8; r++)
                acc[r] = fmaf(xs[r][d], uo, acc[r]);
        }
        #pragma unroll
        for (int r = 0; r < 8; r++) {
            float s = acc[r];
            #pragma unroll
            for (int o = 16; o; o >>= 1) s += __shfl_xor_sync(0xFFFFFFFFu, s, o);
            const int t = t0 + r + 1;              // shift: U[t] uses x[t-1]
            if (lane == 0 && t < T_FRAMES) g_U[t * V_VOC + v] = s;
        }
    }
    if (blockIdx.x == 0 && threadIdx.x < V_VOC) g_U[threadIdx.x] = 0.f;  // U[0] = 0
}

// ---------------------------------------------------------------------------
// Kernel B: colsum S[d] = sum_t x[t][d]   (4 blocks x 256 threads = 1024 = D)
// ---------------------------------------------------------------------------
__global__ void __launch_bounds__(256) kB_colsum(const float* __restrict__ x) {
    const int d = blockIdx.x * 256 + threadIdx.x;
    float a[8];
    #pragma unroll
    for (int r = 0; r < 8; r++) a[r] = 0.f;
    for (int t = 0; t < T_FRAMES; t += 8) {
        #pragma unroll
        for (int r = 0; r < 8; r++)
            a[r] += x[(size_t)(t + r) * D_HID + d];
    }
    g_S[d] = ((a[0] + a[1]) + (a[2] + a[3])) + ((a[4] + a[5]) + (a[6] + a[7]));
}

// ---------------------------------------------------------------------------
// Kernel C: CO[v] = Co[v] . S    (1 block x 128 threads, 4 warps x 7 v each)
// ---------------------------------------------------------------------------
__global__ void __launch_bounds__(128) kC_co(const float* __restrict__ Co) {
    const int warp = threadIdx.x >> 5;
    const int lane = threadIdx.x & 31;
    #pragma unroll
    for (int vi = 0; vi < 7; vi++) {
        const int v = warp * 7 + vi;
        float s = 0.f;
        #pragma unroll 4
        for (int j = 0; j < 32; j++) {
            const int d = j * 32 + lane;
            s = fmaf(__ldg(&Co[v * D_HID + d]), g_S[d], s);
        }
        #pragma unroll
        for (int o = 16; o; o >>= 1) s += __shfl_xor_sync(0xFFFFFFFFu, s, o);
        if (lane == 0) g_CO[v] = s;
    }
}

// ---------------------------------------------------------------------------
// Kernel D: the sequential recurrence. One warp; lane v owns output y[v].
//   y_t[v] = sigmoid( Wo[v,:] . y_{t-1} + U[t][v] + CO[v] )
// Wo row in registers; y broadcast by shuffles; sigmoid = 0.5*tanh(z/2)+0.5
// via single-MUFU tanh.approx. U loads hidden with an 8-deep register ring.
// ---------------------------------------------------------------------------
__global__ void __launch_bounds__(32) kD_recurrence(const float* __restrict__ Wo,
                                                    float* __restrict__ out) {
    const int lane = threadIdx.x;
    const int v = (lane < V_VOC) ? lane : (V_VOC - 1);   // clamp idle lanes

    float w[V_VOC];
    #pragma unroll
    for (int k = 0; k < V_VOC; k++) w[k] = Wo[v * V_VOC + k];
    const float co = g_CO[v];

    // prefetch ring
    float ub[8];
    #pragma unroll
    for (int i = 0; i < 8; i++) ub[i] = g_U[i * V_VOC + v];

    float y = 0.f;

    for (int t = 0; t < T_FRAMES; t += 8) {
        #pragma unroll
        for (int i = 0; i < 8; i++) {
            const float b = ub[i] + co;
            // refill ring for t+i+8 (consumed 8 iters ~1000 cyc later)
            const int tn = t + i + 8;
            ub[i] = (tn < T_FRAMES) ? __ldg(&g_U[tn * V_VOC + v]) : 0.f;

            float a0 = 0.f, a1 = 0.f, a2 = 0.f, a3 = 0.f;
            #pragma unroll
            for (int k = 0; k < V_VOC; k += 4) {   // 28 = 7 x 4
                a0 = fmaf(w[k + 0], __shfl_sync(0xFFFFFFFFu, y, k + 0), a0);
                a1 = fmaf(w[k + 1], __shfl_sync(0xFFFFFFFFu, y, k + 1), a1);
                a2 = fmaf(w[k + 2], __shfl_sync(0xFFFFFFFFu, y, k + 2), a2);
                a3 = fmaf(w[k + 3], __shfl_sync(0xFFFFFFFFu, y, k + 3), a3);
            }
            const float z = ((a0 + a1) + (a2 + a3)) + b;

            float th;
            asm("tanh.approx.f32 %0, %1;" : "=f"(th) : "f"(0.5f * z));
            y = fmaf(0.5f, th, 0.5f);

            if (lane < V_VOC) out[(t + i) * V_VOC + lane] = y;
        }
    }
}

// ---------------------------------------------------------------------------
extern "C" void kernel_launch(void* const* d_in, const int* in_sizes, int n_in,
                              void* d_out, int out_size) {
    const float* x  = (const float*)d_in[0];   // (1, 2048, 1024)
    // d_in[1] = Wa, d_in[2] = Ua, d_in[3] = Va  -- mathematically dead
    const float* Wo = (const float*)d_in[4];   // (28, 28)
    const float* Uo = (const float*)d_in[5];   // (28, 1024)
    const float* Co = (const float*)d_in[6];   // (28, 1024)
    float* out = (float*)d_out;                // (1, 2048, 28)

    kA_computeU<<<T_FRAMES / 8, 128>>>(x, Uo);
    kB_colsum<<<D_HID / 256, 256>>>(x);
    kC_co<<<1, 128>>>(Co);
    kD_recurrence<<<1, 32>>>(Wo, out);
}

// round 2
// speedup vs baseline: 1.0142x; 1.0142x over previous
#include <cuda_runtime.h>
#include <cuda_fp16.h>

#define T_FRAMES 2048
#define D_HID    1024
#define V_VOC    28

// Scratch (no allocation allowed -> device globals)
__device__ float g_U[T_FRAMES * V_VOC];   // 0.5 * (Uo . x[t-1]); row 0 = 0
__device__ float g_S[D_HID];              // colsum of x over t
__device__ float g_CO[V_VOC];             // 0.5 * (Co @ g_S)

// ---------------------------------------------------------------------------
// Kernel A: U[t+1][v] = 0.5 * (Uo[v] . x[t])
// ---------------------------------------------------------------------------
__global__ void __launch_bounds__(128) kA_computeU(const float* __restrict__ x,
                                                   const float* __restrict__ Uo) {
    __shared__ float xs[8][D_HID];                 // 32 KB
    const int t0 = blockIdx.x * 8;

    const float4* xv = reinterpret_cast<const float4*>(x + (size_t)t0 * D_HID);
    float4* sv = reinterpret_cast<float4*>(&xs[0][0]);
    #pragma unroll
    for (int i = threadIdx.x; i < 8 * D_HID / 4; i += 128)
        sv[i] = xv[i];
    __syncthreads();

    const int warp = threadIdx.x >> 5;
    const int lane = threadIdx.x & 31;

    #pragma unroll
    for (int vi = 0; vi < 7; vi++) {
        const int v = warp * 7 + vi;               // 4 warps * 7 = 28 outputs
        const float* uoRow = Uo + v * D_HID;
        float acc[8];
        #pragma unroll
        for (int r = 0; r < 8; r++) acc[r] = 0.f;

        #pragma unroll 4
        for (int j = 0; j < 32; j++) {
            const int d = j * 32 + lane;
            const float uo = __ldg(&uoRow[d]);
            #pragma unroll
            for (int r = 0; r < 8; r++)
                acc[r] = fmaf(xs[r][d], uo, acc[r]);
        }
        #pragma unroll
        for (int r = 0; r < 8; r++) {
            float s = acc[r];
            #pragma unroll
            for (int o = 16; o; o >>= 1) s += __shfl_xor_sync(0xFFFFFFFFu, s, o);
            const int t = t0 + r + 1;              // shift: U[t] uses x[t-1]
            if (lane == 0 && t < T_FRAMES) g_U[t * V_VOC + v] = 0.5f * s;
        }
    }
    if (blockIdx.x == 0 && threadIdx.x < V_VOC) g_U[threadIdx.x] = 0.f;  // U[0] = 0
}

// ---------------------------------------------------------------------------
// Kernel B: colsum S[d] = sum_t x[t][d]
// ---------------------------------------------------------------------------
__global__ void __launch_bounds__(256) kB_colsum(const float* __restrict__ x) {
    const int d = blockIdx.x * 256 + threadIdx.x;
    float a[8];
    #pragma unroll
    for (int r = 0; r < 8; r++) a[r] = 0.f;
    for (int t = 0; t < T_FRAMES; t += 8) {
        #pragma unroll
        for (int r = 0; r < 8; r++)
            a[r] += x[(size_t)(t + r) * D_HID + d];
    }
    g_S[d] = ((a[0] + a[1]) + (a[2] + a[3])) + ((a[4] + a[5]) + (a[6] + a[7]));
}

// ---------------------------------------------------------------------------
// Kernel C: CO[v] = 0.5 * (Co[v] . S)
// ---------------------------------------------------------------------------
__global__ void __launch_bounds__(128) kC_co(const float* __restrict__ Co) {
    const int warp = threadIdx.x >> 5;
    const int lane = threadIdx.x & 31;
    #pragma unroll
    for (int vi = 0; vi < 7; vi++) {
        const int v = warp * 7 + vi;
        float s = 0.f;
        #pragma unroll 4
        for (int j = 0; j < 32; j++) {
            const int d = j * 32 + lane;
            s = fmaf(__ldg(&Co[v * D_HID + d]), g_S[d], s);
        }
        #pragma unroll
        for (int o = 16; o; o >>= 1) s += __shfl_xor_sync(0xFFFFFFFFu, s, o);
        if (lane == 0) g_CO[v] = 0.5f * s;
    }
}

// ---------------------------------------------------------------------------
// Kernel D: sequential recurrence, fp16x2-packed communication.
// Lane j (0..13) owns the output pair (y[2j], y[2j+1]) as half2.
//   0.5*z[v] = (0.5*Wo[v,:]) . y  +  0.5*U[t][v] + 0.5*CO[v]
//   y[v]     = 0.5*tanh(0.5*z[v]) + 0.5
// 14 SHFL broadcasts + 28 HFMA2 per step; z assembled in fp32.
// ---------------------------------------------------------------------------
__global__ void __launch_bounds__(32) kD_recurrence(const float* __restrict__ Wo,
                                                    float* __restrict__ out) {
    const int lane = threadIdx.x;
    const int j = (lane < 14) ? lane : 13;     // output-pair index (idle lanes clamp)
    const int v0 = 2 * j, v1 = 2 * j + 1;

    // Pre-halved weights as half2 chunks: w0[c] = 0.5*(Wo[v0][2c], Wo[v0][2c+1])
    __half2 w0[14], w1[14];
    #pragma unroll
    for (int c = 0; c < 14; c++) {
        w0[c] = __floats2half2_rn(0.5f * Wo[v0 * V_VOC + 2 * c],
                                  0.5f * Wo[v0 * V_VOC + 2 * c + 1]);
        w1[c] = __floats2half2_rn(0.5f * Wo[v1 * V_VOC + 2 * c],
                                  0.5f * Wo[v1 * V_VOC + 2 * c + 1]);
    }

    const float2 co2 = reinterpret_cast<const float2*>(g_CO)[j];  // pre-halved

    // 8-deep prefetch ring of U pairs (pre-halved)
    const float2* U2 = reinterpret_cast<const float2*>(g_U);
    float2 ub[8];
    #pragma unroll
    for (int i = 0; i < 8; i++) ub[i] = U2[i * 14 + j];

    unsigned yh = 0u;   // half2(0,0): previous y pair

    for (int t = 0; t < T_FRAMES; t += 8) {
        #pragma unroll
        for (int i = 0; i < 8; i++) {
            const float b0 = ub[i].x + co2.x;
            const float b1 = ub[i].y + co2.y;
            const int tn = t + i + 8;
            if (tn < T_FRAMES) ub[i] = __ldg(&U2[tn * 14 + j]);

            // broadcast all 14 y pairs
            unsigned yc[14];
            #pragma unroll
            for (int c = 0; c < 14; c++)
                yc[c] = __shfl_sync(0xFFFFFFFFu, yh, c);

            #define U2H(u) (*reinterpret_cast<const __half2*>(&(u)))
            __half2 a0  = __hmul2(w0[0], U2H(yc[0]));
            __half2 a0b = __hmul2(w0[1], U2H(yc[1]));
            __half2 a1  = __hmul2(w1[0], U2H(yc[0]));
            __half2 a1b = __hmul2(w1[1], U2H(yc[1]));
            #pragma unroll
            for (int c = 2; c < 14; c += 2) {
                a0  = __hfma2(w0[c],     U2H(yc[c]),     a0);
                a0b = __hfma2(w0[c + 1], U2H(yc[c + 1]), a0b);
                a1  = __hfma2(w1[c],     U2H(yc[c]),     a1);
                a1b = __hfma2(w1[c + 1], U2H(yc[c + 1]), a1b);
            }
            #undef U2H
            const __half2 s0 = __hadd2(a0, a0b);
            const __half2 s1 = __hadd2(a1, a1b);

            const float z0 = b0 + (__low2float(s0) + __high2float(s0));
            const float z1 = b1 + (__low2float(s1) + __high2float(s1));

            float th0, th1;
            asm("tanh.approx.f32 %0, %1;" : "=f"(th0) : "f"(z0));
            asm("tanh.approx.f32 %0, %1;" : "=f"(th1) : "f"(z1));
            const float y0 = fmaf(0.5f, th0, 0.5f);
            const float y1 = fmaf(0.5f, th1, 0.5f);

            if (lane < 14)
                reinterpret_cast<float2*>(out + (t + i) * V_VOC)[j] =
                    make_float2(y0, y1);

            const __half2 ny = __floats2half2_rn(y0, y1);
            yh = *reinterpret_cast<const unsigned*>(&ny);
        }
    }
}

// ---------------------------------------------------------------------------
extern "C" void kernel_launch(void* const* d_in, const int* in_sizes, int n_in,
                              void* d_out, int out_size) {
    const float* x  = (const float*)d_in[0];   // (1, 2048, 1024)
    // d_in[1] = Wa, d_in[2] = Ua, d_in[3] = Va  -- mathematically dead
    const float* Wo = (const float*)d_in[4];   // (28, 28)
    const float* Uo = (const float*)d_in[5];   // (28, 1024)
    const float* Co = (const float*)d_in[6];   // (28, 1024)
    float* out = (float*)d_out;                // (1, 2048, 28)

    kA_computeU<<<T_FRAMES / 8, 128>>>(x, Uo);
    kB_colsum<<<D_HID / 256, 256>>>(x);
    kC_co<<<1, 128>>>(Co);
    kD_recurrence<<<1, 32>>>(Wo, out);
}

// round 4
// speedup vs baseline: 1.7372x; 1.7129x over previous
#include <cuda_runtime.h>

#define T_FRAMES 2048
#define D_HID    1024
#define V_VOC    28

// ---------------------------------------------------------------------------
// Device scratch (no allocations allowed)
// ---------------------------------------------------------------------------
__device__ float g_U[T_FRAMES * V_VOC];   // 0.5*(Uo . x[t-1]); row 0: 0, then rewritten by kG
__device__ float g_S[D_HID];              // colsum of x over t
__device__ float g_CO[V_VOC];             // 0.5*(Co @ S)
__device__ float g_minU[V_VOC];
__device__ float g_maxU[V_VOC];
__device__ int   g_class[V_VOC];          // 0 = sat->0, 1 = sat->1, 2 = active
__device__ int   g_m;                     // number of active outputs
__device__ int   g_actV[32];              // active rank -> v (zero padded)
__device__ float g_B[32];                 // per-rank folded bias (zero padded)
__device__ float g_Wh[32 * V_VOC];        // per-rank 0.25*Wo[v, act[j]] (zero padded)

// ---------------------------------------------------------------------------
// Kernel A: g_U[t+1][v] = 0.5 * (Uo[v] . x[t]);  g_U[0][*] = 0
// ---------------------------------------------------------------------------
__global__ void __launch_bounds__(128) kA_computeU(const float* __restrict__ x,
                                                   const float* __restrict__ Uo) {
    __shared__ float xs[8][D_HID];
    const int t0 = blockIdx.x * 8;

    const float4* xv = reinterpret_cast<const float4*>(x + (size_t)t0 * D_HID);
    float4* sv = reinterpret_cast<float4*>(&xs[0][0]);
    #pragma unroll
    for (int i = threadIdx.x; i < 8 * D_HID / 4; i += 128)
        sv[i] = xv[i];
    __syncthreads();

    const int warp = threadIdx.x >> 5;
    const int lane = threadIdx.x & 31;

    #pragma unroll
    for (int vi = 0; vi < 7; vi++) {
        const int v = warp * 7 + vi;
        const float* uoRow = Uo + v * D_HID;
        float acc[8];
        #pragma unroll
        for (int r = 0; r < 8; r++) acc[r] = 0.f;

        #pragma unroll 4
        for (int j = 0; j < 32; j++) {
            const int d = j * 32 + lane;
            const float uo = __ldg(&uoRow[d]);
            #pragma unroll
            for (int r = 0; r < 8; r++)
                acc[r] = fmaf(xs[r][d], uo, acc[r]);
        }
        #pragma unroll
        for (int r = 0; r < 8; r++) {
            float s = acc[r];
            #pragma unroll
            for (int o = 16; o; o >>= 1) s += __shfl_xor_sync(0xFFFFFFFFu, s, o);
            const int t = t0 + r + 1;
            if (lane == 0 && t < T_FRAMES) g_U[t * V_VOC + v] = 0.5f * s;
        }
    }
    if (blockIdx.x == 0 && threadIdx.x < V_VOC) g_U[threadIdx.x] = 0.f;
}

// ---------------------------------------------------------------------------
// Kernel B: colsum S[d] = sum_t x[t][d]
// ---------------------------------------------------------------------------
__global__ void __launch_bounds__(256) kB_colsum(const float* __restrict__ x) {
    const int d = blockIdx.x * 256 + threadIdx.x;
    float a[8];
    #pragma unroll
    for (int r = 0; r < 8; r++) a[r] = 0.f;
    for (int t = 0; t < T_FRAMES; t += 8) {
        #pragma unroll
        for (int r = 0; r < 8; r++)
            a[r] += x[(size_t)(t + r) * D_HID + d];
    }
    g_S[d] = ((a[0] + a[1]) + (a[2] + a[3])) + ((a[4] + a[5]) + (a[6] + a[7]));
}

// ---------------------------------------------------------------------------
// Kernel C: g_CO[v] = 0.5 * (Co[v] . S)
// ---------------------------------------------------------------------------
__global__ void __launch_bounds__(128) kC_co(const float* __restrict__ Co) {
    const int warp = threadIdx.x >> 5;
    const int lane = threadIdx.x & 31;
    #pragma unroll
    for (int vi = 0; vi < 7; vi++) {
        const int v = warp * 7 + vi;
        float s = 0.f;
        #pragma unroll 4
        for (int j = 0; j < 32; j++) {
            const int d = j * 32 + lane;
            s = fmaf(__ldg(&Co[v * D_HID + d]), g_S[d], s);
        }
        #pragma unroll
        for (int o = 16; o; o >>= 1) s += __shfl_xor_sync(0xFFFFFFFFu, s, o);
        if (lane == 0) g_CO[v] = 0.5f * s;
    }
}

// ---------------------------------------------------------------------------
// Kernel F: per-v min/max of g_U over t. One block per v.
// ---------------------------------------------------------------------------
__global__ void __launch_bounds__(256) kF_minmax() {
    const int v = blockIdx.x;
    float mn = 1e30f, mx = -1e30f;
    for (int t = threadIdx.x; t < T_FRAMES; t += 256) {
        const float u = g_U[t * V_VOC + v];
        mn = fminf(mn, u);
        mx = fmaxf(mx, u);
    }
    __shared__ float smn[8], smx[8];
    #pragma unroll
    for (int o = 16; o; o >>= 1) {
        mn = fminf(mn, __shfl_xor_sync(0xFFFFFFFFu, mn, o));
        mx = fmaxf(mx, __shfl_xor_sync(0xFFFFFFFFu, mx, o));
    }
    if ((threadIdx.x & 31) == 0) { smn[threadIdx.x >> 5] = mn; smx[threadIdx.x >> 5] = mx; }
    __syncthreads();
    if (threadIdx.x == 0) {
        #pragma unroll
        for (int w = 1; w < 8; w++) { mn = fminf(mn, smn[w]); mx = fmaxf(mx, smx[w]); }
        g_minU[v] = mn;
        g_maxU[v] = mx;
    }
}

// ---------------------------------------------------------------------------
// Kernel G: classify outputs, build active-set tables. One warp.
// ALL __shfl_sync are executed unconditionally by all 32 lanes (no divergence).
//  s[v,t] = coh + Uh[t,v] + 0.5*Wo[v].y ;  y = sigmoid(2s)
//  saturated if the interval bound of s clears +/-7 (|z|>14).
//  Rewrites g_U[0][v] so t=0 (true y_prev=0) is exact under folded-bias form.
// ---------------------------------------------------------------------------
__global__ void __launch_bounds__(32) kG_classify(const float* __restrict__ Wo) {
    const int lane = threadIdx.x;
    const bool valid = lane < V_VOC;
    const int vIdx = valid ? lane : 0;        // clamp so every lane does real work

    float w[V_VOC];
    float rowNeg = 0.f, rowPos = 0.f;
    #pragma unroll
    for (int k = 0; k < V_VOC; k++) {
        w[k] = Wo[vIdx * V_VOC + k];
        rowNeg += fminf(w[k], 0.f);
        rowPos += fmaxf(w[k], 0.f);
    }
    const float coh  = g_CO[vIdx];
    const float sMin = coh + g_minU[vIdx] + 0.5f * rowNeg;
    const float sMax = coh + g_maxU[vIdx] + 0.5f * rowPos;

    int cls = 2;
    if (sMin > 7.f)  cls = 1;
    if (sMax < -7.f) cls = 0;
    if (!valid)      cls = 0;                 // idle lanes: non-active
    if (valid) g_class[lane] = cls;

    const unsigned amask = __ballot_sync(0xFFFFFFFFu, cls == 2) & 0x0FFFFFFFu;
    const int m = __popc(amask);
    if (lane == 0) g_m = m;

    // broadcast every lane's class (uniform: all lanes execute all shuffles)
    int clsA[V_VOC];
    #pragma unroll
    for (int k = 0; k < V_VOC; k++)
        clsA[k] = __shfl_sync(0xFFFFFFFFu, cls, k);

    float s1 = 0.f;                            // sum of Wo row over sat-1 columns
    #pragma unroll
    for (int k = 0; k < V_VOC; k++)
        if (clsA[k] == 1) s1 += w[k];

    // zero tables, then sync before ranked writes (different lanes, same rows)
    g_B[lane] = 0.f;
    g_actV[lane] = 0;
    #pragma unroll
    for (int c = 0; c < V_VOC; c++) g_Wh[lane * V_VOC + c] = 0.f;
    __syncwarp();

    // active list (each lane materializes it from the ballot mask; no shfl)
    int act[V_VOC];
    int cnt = 0;
    #pragma unroll
    for (int k = 0; k < V_VOC; k++)
        if ((amask >> k) & 1u) act[cnt++] = k;

    if (cls == 2) {                            // no shuffles inside this branch
        const int rank = __popc(amask & ((1u << lane) - 1u));
        float sa = 0.f;
        for (int jj = 0; jj < m; jj++) {
            sa += w[act[jj]];
            g_Wh[rank * V_VOC + jj] = 0.25f * w[act[jj]];
        }
        g_B[rank]   = coh + 0.5f * s1 + 0.25f * sa;
        g_actV[rank] = lane;
    }

    // t=0 exactness: model gives s0 = B + Uh0 - 0.25*sa = coh + 0.5*s1 + Uh0;
    // true s0 = coh  =>  Uh0 = -0.5*s1
    if (valid) g_U[lane] = -0.5f * s1;
}

// ---------------------------------------------------------------------------
// Kernel D: serial recurrence over the active set only (tanh-space carry).
//   th_t = tanh( B + Uh[t][v] + sum_j Wh[j]*th_{t-1,j} ),  th_{-1} = -1
//   y = 0.5*th + 0.5
// ---------------------------------------------------------------------------
template <int M, int NACC>
__device__ __forceinline__ void bodyD(float* __restrict__ out, const int m) {
    const int lane = threadIdx.x;
    const int j = (lane < M) ? lane : 0;
    const bool writer = (lane < m);

    const int   v = g_actV[j];
    const float B = g_B[j];
    float w[M];
    #pragma unroll
    for (int c = 0; c < M; c++) w[c] = g_Wh[j * V_VOC + c];

    float ub[8];
    #pragma unroll
    for (int i = 0; i < 8; i++) ub[i] = g_U[i * V_VOC + v];

    float th = -1.0f;   // encodes y_prev = 0

    for (int t = 0; t < T_FRAMES; t += 8) {
        #pragma unroll
        for (int i = 0; i < 8; i++) {
            const float bias = B + ub[i];
            const int tn = t + i + 8;
            if (tn < T_FRAMES) ub[i] = __ldg(&g_U[tn * V_VOC + v]);

            float thc[M];
            #pragma unroll
            for (int c = 0; c < M; c++)
                thc[c] = __shfl_sync(0xFFFFFFFFu, th, c);

            float a[NACC];
            a[0] = bias;
            #pragma unroll
            for (int q = 1; q < NACC; q++) a[q] = 0.f;
            #pragma unroll
            for (int c = 0; c < M; c++)
                a[c % NACC] = fmaf(w[c], thc[c], a[c % NACC]);
            float s = a[0];
            if (NACC == 2) s = a[0] + a[1];
            if (NACC == 4) s = (a[0] + a[1]) + (a[2] + a[3]);

            asm("tanh.approx.f32 %0, %1;" : "=f"(th) : "f"(s));

            if (writer) out[(t + i) * V_VOC + v] = fmaf(0.5f, th, 0.5f);
        }
    }
}

__global__ void __launch_bounds__(32) kD_recurrence(float* __restrict__ out) {
    const int m = g_m;
    if (m == 0) return;
    if      (m <= 4)  bodyD<4, 2>(out, m);
    else if (m <= 8)  bodyD<8, 4>(out, m);
    else if (m <= 16) bodyD<16, 4>(out, m);
    else              bodyD<28, 4>(out, m);
}

// ---------------------------------------------------------------------------
// Kernel H: exact fill of saturated elements, fully parallel over (t, v).
//   y[t][v] = sigmoid( 2*(coh + Uh[t][v]) + Wo[v].y[t-1] )
// Active y[t-1] read from out (written by kD); saturated y[t-1] taken as
// its 0/1 constant (error <= 8.3e-7). t=0 uses y_prev=0 and true Uh0=0.
// ---------------------------------------------------------------------------
__global__ void __launch_bounds__(256) kH_satfill(const float* __restrict__ Wo,
                                                  float* __restrict__ out) {
    const int idx = blockIdx.x * 256 + threadIdx.x;      // t*V + v
    const int t = idx / V_VOC;
    const int v = idx % V_VOC;
    if (g_class[v] == 2) return;

    float s;
    if (t == 0) {
        s = g_CO[v];                                     // Uh0(true)=0, y_prev=0
    } else {
        const float* yprev = out + (t - 1) * V_VOC;
        float dot = 0.f;
        #pragma unroll
        for (int k = 0; k < V_VOC; k++) {
            const int ck = g_class[k];
            const float yk = (ck == 2) ? yprev[k] : (float)ck;
            dot = fmaf(Wo[v * V_VOC + k], yk, dot);
        }
        s = g_CO[v] + g_U[t * V_VOC + v] + 0.5f * dot;
    }
    const float z = 2.f * s;
    float y;
    if (z >= 0.f) { y = 1.f / (1.f + __expf(-z)); }
    else          { const float e = __expf(z); y = e / (1.f + e); }
    out[idx] = y;
}

// ---------------------------------------------------------------------------
extern "C" void kernel_launch(void* const* d_in, const int* in_sizes, int n_in,
                              void* d_out, int out_size) {
    const float* x  = (const float*)d_in[0];   // (1, 2048, 1024)
    // d_in[1..3] = Wa, Ua, Va : mathematically dead (softmax over size-1 axis)
    const float* Wo = (const float*)d_in[4];   // (28, 28)
    const float* Uo = (const float*)d_in[5];   // (28, 1024)
    const float* Co = (const float*)d_in[6];   // (28, 1024)
    float* out = (float*)d_out;                // (1, 2048, 28)

    kA_computeU<<<T_FRAMES / 8, 128>>>(x, Uo);
    kB_colsum<<<D_HID / 256, 256>>>(x);
    kC_co<<<1, 128>>>(Co);
    kF_minmax<<<V_VOC, 256>>>();
    kG_classify<<<1, 32>>>(Wo);
    kD_recurrence<<<1, 32>>>(out);
    kH_satfill<<<(T_FRAMES * V_VOC) / 256, 256>>>(Wo, out);
}

// round 5
// speedup vs baseline: 1.7545x; 1.0099x over previous
#include <cuda_runtime.h>

#define T_FRAMES 2048
#define D_HID    1024
#define V_VOC    28

// ---------------------------------------------------------------------------
// Device scratch (no allocations allowed)
// ---------------------------------------------------------------------------
__device__ float g_U[T_FRAMES * V_VOC];   // 0.5*(Uo . x[t-1]); row 0: 0, then rewritten by kG
__device__ float g_S[D_HID];              // colsum of x over t
__device__ float g_CO[V_VOC];             // 0.5*(Co @ S)
__device__ float g_minU[V_VOC];
__device__ float g_maxU[V_VOC];
__device__ int   g_class[V_VOC];          // 0 = sat->0, 1 = sat->1, 2 = active
__device__ int   g_m;                     // number of active outputs
__device__ int   g_actV[32];              // active rank -> v (zero padded)
__device__ float g_B[32];                 // per-rank folded bias (zero padded)
__device__ float g_Wh[32 * V_VOC];        // per-rank 0.25*Wo[v, act[j]] (zero padded)

// ---------------------------------------------------------------------------
// Kernel A: g_U[t+1][v] = 0.5 * (Uo[v] . x[t]);  g_U[0][*] = 0
// ---------------------------------------------------------------------------
__global__ void __launch_bounds__(128) kA_computeU(const float* __restrict__ x,
                                                   const float* __restrict__ Uo) {
    __shared__ float xs[8][D_HID];
    const int t0 = blockIdx.x * 8;

    const float4* xv = reinterpret_cast<const float4*>(x + (size_t)t0 * D_HID);
    float4* sv = reinterpret_cast<float4*>(&xs[0][0]);
    #pragma unroll
    for (int i = threadIdx.x; i < 8 * D_HID / 4; i += 128)
        sv[i] = xv[i];
    __syncthreads();

    const int warp = threadIdx.x >> 5;
    const int lane = threadIdx.x & 31;

    #pragma unroll
    for (int vi = 0; vi < 7; vi++) {
        const int v = warp * 7 + vi;
        const float* uoRow = Uo + v * D_HID;
        float acc[8];
        #pragma unroll
        for (int r = 0; r < 8; r++) acc[r] = 0.f;

        #pragma unroll 4
        for (int j = 0; j < 32; j++) {
            const int d = j * 32 + lane;
            const float uo = __ldg(&uoRow[d]);
            #pragma unroll
            for (int r = 0; r < 8; r++)
                acc[r] = fmaf(xs[r][d], uo, acc[r]);
        }
        #pragma unroll
        for (int r = 0; r < 8; r++) {
            float s = acc[r];
            #pragma unroll
            for (int o = 16; o; o >>= 1) s += __shfl_xor_sync(0xFFFFFFFFu, s, o);
            const int t = t0 + r + 1;
            if (lane == 0 && t < T_FRAMES) g_U[t * V_VOC + v] = 0.5f * s;
        }
    }
    if (blockIdx.x == 0 && threadIdx.x < V_VOC) g_U[threadIdx.x] = 0.f;
}

// ---------------------------------------------------------------------------
// Kernel B: colsum S[d] = sum_t x[t][d]
// ---------------------------------------------------------------------------
__global__ void __launch_bounds__(256) kB_colsum(const float* __restrict__ x) {
    const int d = blockIdx.x * 256 + threadIdx.x;
    float a[8];
    #pragma unroll
    for (int r = 0; r < 8; r++) a[r] = 0.f;
    for (int t = 0; t < T_FRAMES; t += 8) {
        #pragma unroll
        for (int r = 0; r < 8; r++)
            a[r] += x[(size_t)(t + r) * D_HID + d];
    }
    g_S[d] = ((a[0] + a[1]) + (a[2] + a[3])) + ((a[4] + a[5]) + (a[6] + a[7]));
}

// ---------------------------------------------------------------------------
// Kernel C: g_CO[v] = 0.5 * (Co[v] . S)
// ---------------------------------------------------------------------------
__global__ void __launch_bounds__(128) kC_co(const float* __restrict__ Co) {
    const int warp = threadIdx.x >> 5;
    const int lane = threadIdx.x & 31;
    #pragma unroll
    for (int vi = 0; vi < 7; vi++) {
        const int v = warp * 7 + vi;
        float s = 0.f;
        #pragma unroll 4
        for (int j = 0; j < 32; j++) {
            const int d = j * 32 + lane;
            s = fmaf(__ldg(&Co[v * D_HID + d]), g_S[d], s);
        }
        #pragma unroll
        for (int o = 16; o; o >>= 1) s += __shfl_xor_sync(0xFFFFFFFFu, s, o);
        if (lane == 0) g_CO[v] = 0.5f * s;
    }
}

// ---------------------------------------------------------------------------
// Kernel F: per-v min/max of g_U over t. One block per v.
// ---------------------------------------------------------------------------
__global__ void __launch_bounds__(256) kF_minmax() {
    const int v = blockIdx.x;
    float mn = 1e30f, mx = -1e30f;
    for (int t = threadIdx.x; t < T_FRAMES; t += 256) {
        const float u = g_U[t * V_VOC + v];
        mn = fminf(mn, u);
        mx = fmaxf(mx, u);
    }
    __shared__ float smn[8], smx[8];
    #pragma unroll
    for (int o = 16; o; o >>= 1) {
        mn = fminf(mn, __shfl_xor_sync(0xFFFFFFFFu, mn, o));
        mx = fmaxf(mx, __shfl_xor_sync(0xFFFFFFFFu, mx, o));
    }
    if ((threadIdx.x & 31) == 0) { smn[threadIdx.x >> 5] = mn; smx[threadIdx.x >> 5] = mx; }
    __syncthreads();
    if (threadIdx.x == 0) {
        #pragma unroll
        for (int w = 1; w < 8; w++) { mn = fminf(mn, smn[w]); mx = fmaxf(mx, smx[w]); }
        g_minU[v] = mn;
        g_maxU[v] = mx;
    }
}

// ---------------------------------------------------------------------------
// Kernel G: classify outputs, build active-set tables. One warp.
// ALL __shfl_sync are executed unconditionally by all 32 lanes (no divergence).
//  s[v,t] = coh + Uh[t,v] + 0.5*Wo[v].y ;  y = sigmoid(2s)
//  saturated if the interval bound of s clears +/-7 (|z|>14).
//  Rewrites g_U[0][v] so t=0 (true y_prev=0) is exact under folded-bias form.
// ---------------------------------------------------------------------------
__global__ void __launch_bounds__(32) kG_classify(const float* __restrict__ Wo) {
    const int lane = threadIdx.x;
    const bool valid = lane < V_VOC;
    const int vIdx = valid ? lane : 0;        // clamp so every lane does real work

    float w[V_VOC];
    float rowNeg = 0.f, rowPos = 0.f;
    #pragma unroll
    for (int k = 0; k < V_VOC; k++) {
        w[k] = Wo[vIdx * V_VOC + k];
        rowNeg += fminf(w[k], 0.f);
        rowPos += fmaxf(w[k], 0.f);
    }
    const float coh  = g_CO[vIdx];
    const float sMin = coh + g_minU[vIdx] + 0.5f * rowNeg;
    const float sMax = coh + g_maxU[vIdx] + 0.5f * rowPos;

    int cls = 2;
    if (sMin > 7.f)  cls = 1;
    if (sMax < -7.f) cls = 0;
    if (!valid)      cls = 0;                 // idle lanes: non-active
    if (valid) g_class[lane] = cls;

    const unsigned amask = __ballot_sync(0xFFFFFFFFu, cls == 2) & 0x0FFFFFFFu;
    const int m = __popc(amask);
    if (lane == 0) g_m = m;

    // broadcast every lane's class (uniform: all lanes execute all shuffles)
    int clsA[V_VOC];
    #pragma unroll
    for (int k = 0; k < V_VOC; k++)
        clsA[k] = __shfl_sync(0xFFFFFFFFu, cls, k);

    float s1 = 0.f;                            // sum of Wo row over sat-1 columns
    #pragma unroll
    for (int k = 0; k < V_VOC; k++)
        if (clsA[k] == 1) s1 += w[k];

    // zero tables, then sync before ranked writes (different lanes, same rows)
    g_B[lane] = 0.f;
    g_actV[lane] = 0;
    #pragma unroll
    for (int c = 0; c < V_VOC; c++) g_Wh[lane * V_VOC + c] = 0.f;
    __syncwarp();

    // active list (each lane materializes it from the ballot mask; no shfl)
    int act[V_VOC];
    int cnt = 0;
    #pragma unroll
    for (int k = 0; k < V_VOC; k++)
        if ((amask >> k) & 1u) act[cnt++] = k;

    if (cls == 2) {                            // no shuffles inside this branch
        const int rank = __popc(amask & ((1u << lane) - 1u));
        float sa = 0.f;
        for (int jj = 0; jj < m; jj++) {
            sa += w[act[jj]];
            g_Wh[rank * V_VOC + jj] = 0.25f * w[act[jj]];
        }
        g_B[rank]   = coh + 0.5f * s1 + 0.25f * sa;
        g_actV[rank] = lane;
    }

    // t=0 exactness: model gives s0 = B + Uh0 - 0.25*sa = coh + 0.5*s1 + Uh0;
    // true s0 = coh  =>  Uh0 = -0.5*s1
    if (valid) g_U[lane] = -0.5f * s1;
}

// ---------------------------------------------------------------------------
// Kernel D: serial recurrence over the active set only (tanh-space carry).
//   th_t = tanh( B + Uh[t][v] + sum_j Wh[j]*th_{t-1,j} ),  th_{-1} = -1
//   y = 0.5*th + 0.5
// ---------------------------------------------------------------------------
template <int M, int NACC>
__device__ __forceinline__ void bodyD(float* __restrict__ out, const int m) {
    const int lane = threadIdx.x;
    const int j = (lane < M) ? lane : 0;
    const bool writer = (lane < m);

    const int   v = g_actV[j];
    const float B = g_B[j];
    float w[M];
    #pragma unroll
    for (int c = 0; c < M; c++) w[c] = g_Wh[j * V_VOC + c];

    float ub[8];
    #pragma unroll
    for (int i = 0; i < 8; i++) ub[i] = g_U[i * V_VOC + v];

    float th = -1.0f;   // encodes y_prev = 0

    for (int t = 0; t < T_FRAMES; t += 8) {
        #pragma unroll
        for (int i = 0; i < 8; i++) {
            const float bias = B + ub[i];
            const int tn = t + i + 8;
            if (tn < T_FRAMES) ub[i] = __ldg(&g_U[tn * V_VOC + v]);

            float thc[M];
            #pragma unroll
            for (int c = 0; c < M; c++)
                thc[c] = __shfl_sync(0xFFFFFFFFu, th, c);

            float a[NACC];
            a[0] = bias;
            #pragma unroll
            for (int q = 1; q < NACC; q++) a[q] = 0.f;
            #pragma unroll
            for (int c = 0; c < M; c++)
                a[c % NACC] = fmaf(w[c], thc[c], a[c % NACC]);
            float s = a[0];
            if (NACC == 2) s = a[0] + a[1];
            if (NACC == 4) s = (a[0] + a[1]) + (a[2] + a[3]);

            asm("tanh.approx.f32 %0, %1;" : "=f"(th) : "f"(s));

            if (writer) out[(t + i) * V_VOC + v] = fmaf(0.5f, th, 0.5f);
        }
    }
}

__global__ void __launch_bounds__(32) kD_recurrence(float* __restrict__ out) {
    const int m = g_m;
    if (m == 0) return;
    if      (m <= 4)  bodyD<4, 2>(out, m);
    else if (m <= 8)  bodyD<8, 4>(out, m);
    else if (m <= 16) bodyD<16, 4>(out, m);
    else              bodyD<28, 4>(out, m);
}

// ---------------------------------------------------------------------------
// Kernel H: exact fill of saturated elements, fully parallel over (t, v).
//   y[t][v] = sigmoid( 2*(coh + Uh[t][v]) + Wo[v].y[t-1] )
// Active y[t-1] read from out (written by kD); saturated y[t-1] taken as
// its 0/1 constant (error <= 8.3e-7). t=0 uses y_prev=0 and true Uh0=0.
// ---------------------------------------------------------------------------
__global__ void __launch_bounds__(256) kH_satfill(const float* __restrict__ Wo,
                                                  float* __restrict__ out) {
    const int idx = blockIdx.x * 256 + threadIdx.x;      // t*V + v
    const int t = idx / V_VOC;
    const int v = idx % V_VOC;
    if (g_class[v] == 2) return;

    float s;
    if (t == 0) {
        s = g_CO[v];                                     // Uh0(true)=0, y_prev=0
    } else {
        const float* yprev = out + (t - 1) * V_VOC;
        float dot = 0.f;
        #pragma unroll
        for (int k = 0; k < V_VOC; k++) {
            const int ck = g_class[k];
            const float yk = (ck == 2) ? yprev[k] : (float)ck;
            dot = fmaf(Wo[v * V_VOC + k], yk, dot);
        }
        s = g_CO[v] + g_U[t * V_VOC + v] + 0.5f * dot;
    }
    const float z = 2.f * s;
    float y;
    if (z >= 0.f) { y = 1.f / (1.f + __expf(-z)); }
    else          { const float e = __expf(z); y = e / (1.f + e); }
    out[idx] = y;
}

// ---------------------------------------------------------------------------
extern "C" void kernel_launch(void* const* d_in, const int* in_sizes, int n_in,
                              void* d_out, int out_size) {
    const float* x  = (const float*)d_in[0];   // (1, 2048, 1024)
    // d_in[1..3] = Wa, Ua, Va : mathematically dead (softmax over size-1 axis)
    const float* Wo = (const float*)d_in[4];   // (28, 28)
    const float* Uo = (const float*)d_in[5];   // (28, 1024)
    const float* Co = (const float*)d_in[6];   // (28, 1024)
    float* out = (float*)d_out;                // (1, 2048, 28)

    kA_computeU<<<T_FRAMES / 8, 128>>>(x, Uo);
    kB_colsum<<<D_HID / 256, 256>>>(x);
    kC_co<<<1, 128>>>(Co);
    kF_minmax<<<V_VOC, 256>>>();
    kG_classify<<<1, 32>>>(Wo);
    kD_recurrence<<<1, 32>>>(out);
    kH_satfill<<<(T_FRAMES * V_VOC) / 256, 256>>>(Wo, out);
}

// round 6
// speedup vs baseline: 4.4286x; 2.5241x over previous
#include <cuda_runtime.h>

#define T_FRAMES 2048
#define D_HID    1024
#define V_VOC    28
#define CHUNK    64
#define HALO     16
#define NCHUNK   (T_FRAMES / CHUNK)

// ---------------------------------------------------------------------------
// Device scratch
// ---------------------------------------------------------------------------
__device__ float g_U[T_FRAMES * V_VOC];   // 0.5*(Uo . x[t-1]); row 0 rewritten by kMeta
__device__ float g_S[D_HID];
__device__ float g_CO[V_VOC];             // 0.5*(Co @ S)
__device__ float g_partMn[V_VOC * 256];   // per-kA-block min of 0.5*U
__device__ float g_partMx[V_VOC * 256];
__device__ float g_minU[V_VOC];
__device__ float g_maxU[V_VOC];
__device__ int   g_class[V_VOC];          // 0 sat->0, 1 sat->1, 2 active
__device__ int   g_m;
__device__ int   g_useSerial;
__device__ int   g_actV[32];
__device__ float g_B[32];
__device__ float g_Wh[32 * V_VOC];        // 0.25*Wo[v, act[j]]

// ---------------------------------------------------------------------------
// Kernel A: g_U[t+1][v] = 0.5*(Uo[v] . x[t]) + per-block min/max partials
// ---------------------------------------------------------------------------
__global__ void __launch_bounds__(128) kA_computeU(const float* __restrict__ x,
                                                   const float* __restrict__ Uo) {
    __shared__ float xs[8][D_HID];
    const int t0 = blockIdx.x * 8;

    const float4* xv = reinterpret_cast<const float4*>(x + (size_t)t0 * D_HID);
    float4* sv = reinterpret_cast<float4*>(&xs[0][0]);
    #pragma unroll
    for (int i = threadIdx.x; i < 8 * D_HID / 4; i += 128)
        sv[i] = xv[i];
    __syncthreads();

    const int warp = threadIdx.x >> 5;
    const int lane = threadIdx.x & 31;

    #pragma unroll
    for (int vi = 0; vi < 7; vi++) {
        const int v = warp * 7 + vi;
        const float* uoRow = Uo + v * D_HID;
        float acc[8];
        #pragma unroll
        for (int r = 0; r < 8; r++) acc[r] = 0.f;

        #pragma unroll 4
        for (int j = 0; j < 32; j++) {
            const int d = j * 32 + lane;
            const float uo = __ldg(&uoRow[d]);
            #pragma unroll
            for (int r = 0; r < 8; r++)
                acc[r] = fmaf(xs[r][d], uo, acc[r]);
        }
        float mn = 1e30f, mx = -1e30f;
        #pragma unroll
        for (int r = 0; r < 8; r++) {
            float s = acc[r];
            #pragma unroll
            for (int o = 16; o; o >>= 1) s += __shfl_xor_sync(0xFFFFFFFFu, s, o);
            const int t = t0 + r + 1;
            if (lane == 0 && t < T_FRAMES) {
                const float uh = 0.5f * s;
                g_U[t * V_VOC + v] = uh;
                mn = fminf(mn, uh);
                mx = fmaxf(mx, uh);
            }
        }
        if (lane == 0) {
            g_partMn[v * 256 + blockIdx.x] = mn;
            g_partMx[v * 256 + blockIdx.x] = mx;
        }
    }
}

// ---------------------------------------------------------------------------
// Kernel B: colsum S[d] = sum_t x[t][d]
// ---------------------------------------------------------------------------
__global__ void __launch_bounds__(256) kB_colsum(const float* __restrict__ x) {
    const int d = blockIdx.x * 256 + threadIdx.x;
    float a[8];
    #pragma unroll
    for (int r = 0; r < 8; r++) a[r] = 0.f;
    for (int t = 0; t < T_FRAMES; t += 8) {
        #pragma unroll
        for (int r = 0; r < 8; r++)
            a[r] += x[(size_t)(t + r) * D_HID + d];
    }
    g_S[d] = ((a[0] + a[1]) + (a[2] + a[3])) + ((a[4] + a[5]) + (a[6] + a[7]));
}

// ---------------------------------------------------------------------------
// Kernel Meta: CO + min/max reduce + classify + tables.  1 block, 896 threads.
// ---------------------------------------------------------------------------
__global__ void __launch_bounds__(896) kMeta(const float* __restrict__ Co,
                                             const float* __restrict__ Wo) {
    const int warp = threadIdx.x >> 5;   // 0..27 == v
    const int lane = threadIdx.x & 31;

    // phase A: g_CO[v] = 0.5 * (Co[v] . S)
    {
        float s = 0.f;
        #pragma unroll 4
        for (int j = 0; j < 32; j++) {
            const int d = j * 32 + lane;
            s = fmaf(__ldg(&Co[warp * D_HID + d]), g_S[d], s);
        }
        #pragma unroll
        for (int o = 16; o; o >>= 1) s += __shfl_xor_sync(0xFFFFFFFFu, s, o);
        if (lane == 0) g_CO[warp] = 0.5f * s;
    }
    // phase B: reduce partial min/max (include t=0 value 0)
    {
        float mn = 0.f, mx = 0.f;
        #pragma unroll
        for (int i = 0; i < 8; i++) {
            mn = fminf(mn, g_partMn[warp * 256 + lane + 32 * i]);
            mx = fmaxf(mx, g_partMx[warp * 256 + lane + 32 * i]);
        }
        #pragma unroll
        for (int o = 16; o; o >>= 1) {
            mn = fminf(mn, __shfl_xor_sync(0xFFFFFFFFu, mn, o));
            mx = fmaxf(mx, __shfl_xor_sync(0xFFFFFFFFu, mx, o));
        }
        if (lane == 0) { g_minU[warp] = mn; g_maxU[warp] = mx; }
    }
    __syncthreads();
    if (warp != 0) return;

    // phase C (warp 0 only): classification + active tables. All shuffles uniform.
    const bool valid = lane < V_VOC;
    const int vIdx = valid ? lane : 0;

    float w[V_VOC];
    float rowNeg = 0.f, rowPos = 0.f;
    #pragma unroll
    for (int k = 0; k < V_VOC; k++) {
        w[k] = Wo[vIdx * V_VOC + k];
        rowNeg += fminf(w[k], 0.f);
        rowPos += fmaxf(w[k], 0.f);
    }
    const float coh  = g_CO[vIdx];
    const float sMin = coh + g_minU[vIdx] + 0.5f * rowNeg;
    const float sMax = coh + g_maxU[vIdx] + 0.5f * rowPos;

    int cls = 2;
    if (sMin > 7.f)  cls = 1;
    if (sMax < -7.f) cls = 0;
    if (!valid)      cls = 0;
    if (valid) g_class[lane] = cls;

    const unsigned amask = __ballot_sync(0xFFFFFFFFu, cls == 2) & 0x0FFFFFFFu;
    const int m = __popc(amask);
    if (lane == 0) g_m = m;

    int clsA[V_VOC];
    #pragma unroll
    for (int k = 0; k < V_VOC; k++)
        clsA[k] = __shfl_sync(0xFFFFFFFFu, cls, k);

    float s1 = 0.f;
    #pragma unroll
    for (int k = 0; k < V_VOC; k++)
        if (clsA[k] == 1) s1 += w[k];

    g_B[lane] = 0.f;
    g_actV[lane] = 0;
    #pragma unroll
    for (int c = 0; c < V_VOC; c++) g_Wh[lane * V_VOC + c] = 0.f;
    __syncwarp();

    int act[V_VOC];
    int cnt = 0;
    #pragma unroll
    for (int k = 0; k < V_VOC; k++)
        if ((amask >> k) & 1u) act[cnt++] = k;

    float qrow = 0.f;
    if (cls == 2) {                           // no shuffles inside
        const int rank = __popc(amask & ((1u << lane) - 1u));
        float sa = 0.f;
        for (int jj = 0; jj < m; jj++) {
            const float wa = w[act[jj]];
            sa += wa;
            g_Wh[rank * V_VOC + jj] = 0.25f * wa;
            qrow += 0.25f * fabsf(wa);
        }
        g_B[rank]    = coh + 0.5f * s1 + 0.25f * sa;
        g_actV[rank] = lane;
    }
    #pragma unroll
    for (int o = 16; o; o >>= 1)
        qrow = fmaxf(qrow, __shfl_xor_sync(0xFFFFFFFFu, qrow, o));
    if (lane == 0) g_useSerial = (m > 16 || qrow > 0.40f) ? 1 : 0;

    // t=0 exactness under folded-bias form: Uh0 = -0.5*s1
    if (valid) g_U[lane] = -0.5f * s1;
}

// ---------------------------------------------------------------------------
// One recurrence step (shared by chunked + serial paths)
// ---------------------------------------------------------------------------
template <int M, int NACC>
__device__ __forceinline__ float stepFn(const float* __restrict__ w,
                                        float th, float bias) {
    float thc[M];
    #pragma unroll
    for (int c = 0; c < M; c++)
        thc[c] = __shfl_sync(0xFFFFFFFFu, th, c);
    float a[NACC];
    a[0] = bias;
    #pragma unroll
    for (int q = 1; q < NACC; q++) a[q] = 0.f;
    #pragma unroll
    for (int c = 0; c < M; c++)
        a[c % NACC] = fmaf(w[c], thc[c], a[c % NACC]);
    float s = a[0];
    if (NACC == 2) s = a[0] + a[1];
    if (NACC == 4) s = (a[0] + a[1]) + (a[2] + a[3]);
    float nth;
    asm("tanh.approx.f32 %0, %1;" : "=f"(nth) : "f"(s));
    return nth;
}

// ---------------------------------------------------------------------------
// Chunked solver: block b handles t in [b*CHUNK, (b+1)*CHUNK), warming up
// over HALO steps from the decoupled guess (state error decays by q/step).
// ---------------------------------------------------------------------------
template <int M, int NACC>
__device__ __forceinline__ void chunkBody(float* __restrict__ out) {
    const int lane = threadIdx.x;
    const int j = (lane < M) ? lane : 0;
    const bool writer = (lane < g_m);

    const int   v = g_actV[j];
    const float B = g_B[j];
    float w[M];
    #pragma unroll
    for (int c = 0; c < M; c++) w[c] = g_Wh[j * V_VOC + c];

    const int t0 = blockIdx.x * CHUNK;
    const int ts = (blockIdx.x == 0) ? 0 : (t0 - HALO);
    const int te = t0 + CHUNK;

    float th;
    if (blockIdx.x == 0) {
        th = -1.f;                                  // y_prev = 0 exactly
    } else {
        const float s0 = B + __ldg(&g_U[(ts - 1) * V_VOC + v]);
        asm("tanh.approx.f32 %0, %1;" : "=f"(th) : "f"(s0));   // guess, err <= q
    }

    float ub[8];
    #pragma unroll
    for (int i = 0; i < 8; i++) ub[i] = __ldg(&g_U[(ts + i) * V_VOC + v]);

    for (int t = ts; t < te; t += 8) {
        #pragma unroll
        for (int i = 0; i < 8; i++) {
            const float bias = B + ub[i];
            const int tn = t + i + 8;
            if (tn < te) ub[i] = __ldg(&g_U[tn * V_VOC + v]);
            th = stepFn<M, NACC>(w, th, bias);
            if (writer && (t + i) >= t0)
                out[(t + i) * V_VOC + v] = fmaf(0.5f, th, 0.5f);
        }
    }
}

// Full-serial fallback (runs only if g_useSerial; block 0 only)
template <int M, int NACC>
__device__ __forceinline__ void serialBody(float* __restrict__ out, const int m) {
    const int lane = threadIdx.x;
    const int j = (lane < M) ? lane : 0;
    const bool writer = (lane < m);

    const int   v = g_actV[j];
    const float B = g_B[j];
    float w[M];
    #pragma unroll
    for (int c = 0; c < M; c++) w[c] = g_Wh[j * V_VOC + c];

    float ub[8];
    #pragma unroll
    for (int i = 0; i < 8; i++) ub[i] = g_U[i * V_VOC + v];

    float th = -1.0f;
    for (int t = 0; t < T_FRAMES; t += 8) {
        #pragma unroll
        for (int i = 0; i < 8; i++) {
            const float bias = B + ub[i];
            const int tn = t + i + 8;
            if (tn < T_FRAMES) ub[i] = __ldg(&g_U[tn * V_VOC + v]);
            th = stepFn<M, NACC>(w, th, bias);
            if (writer) out[(t + i) * V_VOC + v] = fmaf(0.5f, th, 0.5f);
        }
    }
}

__global__ void __launch_bounds__(32) kD_solve(float* __restrict__ out) {
    const int m = g_m;
    if (m == 0) return;
    if (g_useSerial) {
        if (blockIdx.x != 0) return;
        serialBody<28, 4>(out, m);
        return;
    }
    if      (m <= 4) chunkBody<4, 2>(out);
    else if (m <= 8) chunkBody<8, 4>(out);
    else             chunkBody<16, 4>(out);
}

// ---------------------------------------------------------------------------
// Kernel H: exact parallel fill of saturated outputs.
// ---------------------------------------------------------------------------
__global__ void __launch_bounds__(256) kH_satfill(const float* __restrict__ Wo,
                                                  float* __restrict__ out) {
    const int idx = blockIdx.x * 256 + threadIdx.x;
    const int t = idx / V_VOC;
    const int v = idx % V_VOC;
    if (g_class[v] == 2) return;

    float s;
    if (t == 0) {
        s = g_CO[v];
    } else {
        const float* yprev = out + (t - 1) * V_VOC;
        float dot = 0.f;
        #pragma unroll
        for (int k = 0; k < V_VOC; k++) {
            const int ck = g_class[k];
            const float yk = (ck == 2) ? yprev[k] : (float)ck;
            dot = fmaf(Wo[v * V_VOC + k], yk, dot);
        }
        s = g_CO[v] + g_U[t * V_VOC + v] + 0.5f * dot;
    }
    const float z = 2.f * s;
    float y;
    if (z >= 0.f) { y = 1.f / (1.f + __expf(-z)); }
    else          { const float e = __expf(z); y = e / (1.f + e); }
    out[idx] = y;
}

// ---------------------------------------------------------------------------
extern "C" void kernel_launch(void* const* d_in, const int* in_sizes, int n_in,
                              void* d_out, int out_size) {
    const float* x  = (const float*)d_in[0];   // (1, 2048, 1024)
    // d_in[1..3] = Wa, Ua, Va : mathematically dead (softmax over size-1 axis)
    const float* Wo = (const float*)d_in[4];   // (28, 28)
    const float* Uo = (const float*)d_in[5];   // (28, 1024)
    const float* Co = (const float*)d_in[6];   // (28, 1024)
    float* out = (float*)d_out;                // (1, 2048, 28)

    kA_computeU<<<T_FRAMES / 8, 128>>>(x, Uo);
    kB_colsum<<<D_HID / 256, 256>>>(x);
    kMeta<<<1, 896>>>(Co, Wo);
    kD_solve<<<NCHUNK, 32>>>(out);
    kH_satfill<<<(T_FRAMES * V_VOC) / 256, 256>>>(Wo, out);
}

// round 7
// speedup vs baseline: 8.5264x; 1.9253x over previous
#include <cuda_runtime.h>

#define T_FRAMES 2048
#define D_HID    1024
#define V_VOC    28
#define CHUNK    32
#define NCHUNK   (T_FRAMES / CHUNK)

// ---------------------------------------------------------------------------
// Device scratch
// ---------------------------------------------------------------------------
__device__ float g_U[T_FRAMES * V_VOC];   // 0.5*(Uo . x[t-1]); row 0 rewritten by kMeta
__device__ float g_S[D_HID];              // colsum of x (atomic-accumulated; memset to 0)
__device__ float g_CO[V_VOC];             // 0.5*(Co @ S)
__device__ float g_partMn[V_VOC * 256];
__device__ float g_partMx[V_VOC * 256];
__device__ int   g_class[V_VOC];          // 0 sat->0, 1 sat->1, 2 active
__device__ int   g_m;
__device__ int   g_useSerial;
__device__ int   g_halo;                  // 8 or 16, from measured contraction q
__device__ int   g_actV[32];
__device__ float g_B[32];
__device__ float g_Wh[32 * V_VOC];        // 0.25*Wo[v, act[j]]

// ---------------------------------------------------------------------------
// Kernel A: g_U[t+1][v] = 0.5*(Uo[v] . x[t]); fused partial colsum (atomics)
// and per-block min/max partials of 0.5*U.
// ---------------------------------------------------------------------------
__global__ void __launch_bounds__(128) kA_computeU(const float* __restrict__ x,
                                                   const float* __restrict__ Uo) {
    __shared__ float xs[8][D_HID];
    const int t0 = blockIdx.x * 8;

    const float4* xv = reinterpret_cast<const float4*>(x + (size_t)t0 * D_HID);
    float4* sv = reinterpret_cast<float4*>(&xs[0][0]);
    #pragma unroll
    for (int i = threadIdx.x; i < 8 * D_HID / 4; i += 128)
        sv[i] = xv[i];
    __syncthreads();

    const int warp = threadIdx.x >> 5;
    const int lane = threadIdx.x & 31;

    // fused colsum: thread handles d = threadIdx.x + 128*i (conflict-free LDS)
    #pragma unroll
    for (int i = 0; i < 8; i++) {
        const int d = threadIdx.x + 128 * i;
        float s = 0.f;
        #pragma unroll
        for (int r = 0; r < 8; r++) s += xs[r][d];
        atomicAdd(&g_S[d], s);
    }

    #pragma unroll
    for (int vi = 0; vi < 7; vi++) {
        const int v = warp * 7 + vi;
        const float* uoRow = Uo + v * D_HID;
        float acc[8];
        #pragma unroll
        for (int r = 0; r < 8; r++) acc[r] = 0.f;

        #pragma unroll 4
        for (int j = 0; j < 32; j++) {
            const int d = j * 32 + lane;
            const float uo = __ldg(&uoRow[d]);
            #pragma unroll
            for (int r = 0; r < 8; r++)
                acc[r] = fmaf(xs[r][d], uo, acc[r]);
        }
        float mn = 1e30f, mx = -1e30f;
        #pragma unroll
        for (int r = 0; r < 8; r++) {
            float s = acc[r];
            #pragma unroll
            for (int o = 16; o; o >>= 1) s += __shfl_xor_sync(0xFFFFFFFFu, s, o);
            const int t = t0 + r + 1;
            if (lane == 0 && t < T_FRAMES) {
                const float uh = 0.5f * s;
                g_U[t * V_VOC + v] = uh;
                mn = fminf(mn, uh);
                mx = fmaxf(mx, uh);
            }
        }
        if (lane == 0) {
            g_partMn[v * 256 + blockIdx.x] = mn;
            g_partMx[v * 256 + blockIdx.x] = mx;
        }
    }
}

// ---------------------------------------------------------------------------
// Kernel Meta: CO + min/max reduce + classify + tables. 1 block, 1024 threads.
// ---------------------------------------------------------------------------
__global__ void __launch_bounds__(1024) kMeta(const float* __restrict__ Co,
                                              const float* __restrict__ Wo) {
    const int warp = threadIdx.x >> 5;
    const int lane = threadIdx.x & 31;

    if (warp < V_VOC) {
        // phase A: g_CO[v] = 0.5 * (Co[v] . S)
        float s = 0.f;
        #pragma unroll 4
        for (int j = 0; j < 32; j++) {
            const int d = j * 32 + lane;
            s = fmaf(__ldg(&Co[warp * D_HID + d]), g_S[d], s);
        }
        #pragma unroll
        for (int o = 16; o; o >>= 1) s += __shfl_xor_sync(0xFFFFFFFFu, s, o);
        if (lane == 0) g_CO[warp] = 0.5f * s;

        // phase B: reduce partial min/max (include t=0 value 0)
        float mn = 0.f, mx = 0.f;
        #pragma unroll
        for (int i = 0; i < 8; i++) {
            mn = fminf(mn, g_partMn[warp * 256 + lane + 32 * i]);
            mx = fmaxf(mx, g_partMx[warp * 256 + lane + 32 * i]);
        }
        #pragma unroll
        for (int o = 16; o; o >>= 1) {
            mn = fminf(mn, __shfl_xor_sync(0xFFFFFFFFu, mn, o));
            mx = fmaxf(mx, __shfl_xor_sync(0xFFFFFFFFu, mx, o));
        }
        if (lane == 0) { g_partMn[warp * 256] = mn; g_partMx[warp * 256] = mx; }
    }
    __syncthreads();
    if (warp != 0) return;

    // phase C (warp 0 only). All shuffles uniform across the warp.
    const bool valid = lane < V_VOC;
    const int vIdx = valid ? lane : 0;

    float w[V_VOC];
    float rowNeg = 0.f, rowPos = 0.f;
    #pragma unroll
    for (int k = 0; k < V_VOC; k++) {
        w[k] = Wo[vIdx * V_VOC + k];
        rowNeg += fminf(w[k], 0.f);
        rowPos += fmaxf(w[k], 0.f);
    }
    const float coh  = g_CO[vIdx];
    const float sMin = coh + g_partMn[vIdx * 256] + 0.5f * rowNeg;
    const float sMax = coh + g_partMx[vIdx * 256] + 0.5f * rowPos;

    int cls = 2;
    if (sMin > 7.f)  cls = 1;
    if (sMax < -7.f) cls = 0;
    if (!valid)      cls = 0;
    if (valid) g_class[lane] = cls;

    const unsigned amask = __ballot_sync(0xFFFFFFFFu, cls == 2) & 0x0FFFFFFFu;
    const int m = __popc(amask);
    if (lane == 0) g_m = m;

    int clsA[V_VOC];
    #pragma unroll
    for (int k = 0; k < V_VOC; k++)
        clsA[k] = __shfl_sync(0xFFFFFFFFu, cls, k);

    float s1 = 0.f;
    #pragma unroll
    for (int k = 0; k < V_VOC; k++)
        if (clsA[k] == 1) s1 += w[k];

    g_B[lane] = 0.f;
    g_actV[lane] = 0;
    #pragma unroll
    for (int c = 0; c < V_VOC; c++) g_Wh[lane * V_VOC + c] = 0.f;
    __syncwarp();

    int act[V_VOC];
    int cnt = 0;
    #pragma unroll
    for (int k = 0; k < V_VOC; k++)
        if ((amask >> k) & 1u) act[cnt++] = k;

    float qrow = 0.f;
    if (cls == 2) {                           // no shuffles inside
        const int rank = __popc(amask & ((1u << lane) - 1u));
        float sa = 0.f;
        for (int jj = 0; jj < m; jj++) {
            const float wa = w[act[jj]];
            sa += wa;
            g_Wh[rank * V_VOC + jj] = 0.25f * wa;
            qrow += 0.25f * fabsf(wa);
        }
        g_B[rank]    = coh + 0.5f * s1 + 0.25f * sa;
        g_actV[rank] = lane;
    }
    #pragma unroll
    for (int o = 16; o; o >>= 1)
        qrow = fmaxf(qrow, __shfl_xor_sync(0xFFFFFFFFu, qrow, o));
    if (lane == 0) {
        g_useSerial = (m > 16 || qrow > 0.40f) ? 1 : 0;
        // halo: error <= q^(halo+1); pick 8 if q^9 < 1e-7 else 16
        const float q = fmaxf(qrow, 1e-4f);
        g_halo = (9.f * __logf(q) < -16.2f) ? 8 : 16;
    }

    // t=0 exactness under folded-bias form: Uh0 = -0.5*s1
    if (valid) g_U[lane] = -0.5f * s1;
}

// ---------------------------------------------------------------------------
// One recurrence step
// ---------------------------------------------------------------------------
template <int M, int NACC>
__device__ __forceinline__ float stepFn(const float* __restrict__ w,
                                        float th, float bias) {
    float thc[M];
    #pragma unroll
    for (int c = 0; c < M; c++)
        thc[c] = __shfl_sync(0xFFFFFFFFu, th, c);
    float a[NACC];
    a[0] = bias;
    #pragma unroll
    for (int q = 1; q < NACC; q++) a[q] = 0.f;
    #pragma unroll
    for (int c = 0; c < M; c++)
        a[c % NACC] = fmaf(w[c], thc[c], a[c % NACC]);
    float s = a[0];
    if (NACC == 2) s = a[0] + a[1];
    if (NACC == 4) s = (a[0] + a[1]) + (a[2] + a[3]);
    float nth;
    asm("tanh.approx.f32 %0, %1;" : "=f"(nth) : "f"(s));
    return nth;
}

// ---------------------------------------------------------------------------
// Chunked solver: block b handles t in [b*CHUNK, (b+1)*CHUNK), warming up
// over halo steps from the decoupled guess.
// ---------------------------------------------------------------------------
template <int M, int NACC>
__device__ __forceinline__ void chunkBody(float* __restrict__ out) {
    const int lane = threadIdx.x;
    const int j = (lane < M) ? lane : 0;
    const bool writer = (lane < g_m);

    const int   v = g_actV[j];
    const float B = g_B[j];
    float w[M];
    #pragma unroll
    for (int c = 0; c < M; c++) w[c] = g_Wh[j * V_VOC + c];

    const int halo = g_halo;                       // 8 or 16 (multiple of 8)
    const int t0 = blockIdx.x * CHUNK;
    const int ts = (blockIdx.x == 0) ? 0 : (t0 - halo);
    const int te = t0 + CHUNK;

    float th;
    if (blockIdx.x == 0) {
        th = -1.f;                                 // y_prev = 0 exactly
    } else {
        const float s0 = B + __ldg(&g_U[(ts - 1) * V_VOC + v]);
        asm("tanh.approx.f32 %0, %1;" : "=f"(th) : "f"(s0));   // guess, err <= q
    }

    float ub[8];
    #pragma unroll
    for (int i = 0; i < 8; i++) ub[i] = __ldg(&g_U[(ts + i) * V_VOC + v]);

    for (int t = ts; t < te; t += 8) {
        #pragma unroll
        for (int i = 0; i < 8; i++) {
            const float bias = B + ub[i];
            const int tn = t + i + 8;
            if (tn < te) ub[i] = __ldg(&g_U[tn * V_VOC + v]);
            th = stepFn<M, NACC>(w, th, bias);
            if (writer && (t + i) >= t0)
                out[(t + i) * V_VOC + v] = fmaf(0.5f, th, 0.5f);
        }
    }
}

// Full-serial fallback (block 0 only)
template <int M, int NACC>
__device__ __forceinline__ void serialBody(float* __restrict__ out, const int m) {
    const int lane = threadIdx.x;
    const int j = (lane < M) ? lane : 0;
    const bool writer = (lane < m);

    const int   v = g_actV[j];
    const float B = g_B[j];
    float w[M];
    #pragma unroll
    for (int c = 0; c < M; c++) w[c] = g_Wh[j * V_VOC + c];

    float ub[8];
    #pragma unroll
    for (int i = 0; i < 8; i++) ub[i] = g_U[i * V_VOC + v];

    float th = -1.0f;
    for (int t = 0; t < T_FRAMES; t += 8) {
        #pragma unroll
        for (int i = 0; i < 8; i++) {
            const float bias = B + ub[i];
            const int tn = t + i + 8;
            if (tn < T_FRAMES) ub[i] = __ldg(&g_U[tn * V_VOC + v]);
            th = stepFn<M, NACC>(w, th, bias);
            if (writer) out[(t + i) * V_VOC + v] = fmaf(0.5f, th, 0.5f);
        }
    }
}

__global__ void __launch_bounds__(32) kD_solve(float* __restrict__ out) {
    const int m = g_m;
    if (m == 0) return;
    if (g_useSerial) {
        if (blockIdx.x != 0) return;
        serialBody<28, 4>(out, m);
        return;
    }
    if      (m <= 4) chunkBody<4, 2>(out);
    else if (m <= 8) chunkBody<8, 4>(out);
    else             chunkBody<16, 4>(out);
}

// ---------------------------------------------------------------------------
// Kernel H: exact parallel fill of saturated outputs.
// ---------------------------------------------------------------------------
__global__ void __launch_bounds__(256) kH_satfill(const float* __restrict__ Wo,
                                                  float* __restrict__ out) {
    const int idx = blockIdx.x * 256 + threadIdx.x;
    const int t = idx / V_VOC;
    const int v = idx % V_VOC;
    if (g_class[v] == 2) return;

    float s;
    if (t == 0) {
        s = g_CO[v];
    } else {
        const float* yprev = out + (t - 1) * V_VOC;
        float dot = 0.f;
        #pragma unroll
        for (int k = 0; k < V_VOC; k++) {
            const int ck = g_class[k];
            const float yk = (ck == 2) ? yprev[k] : (float)ck;
            dot = fmaf(Wo[v * V_VOC + k], yk, dot);
        }
        s = g_CO[v] + g_U[t * V_VOC + v] + 0.5f * dot;
    }
    const float z = 2.f * s;
    float y;
    if (z >= 0.f) { y = 1.f / (1.f + __expf(-z)); }
    else          { const float e = __expf(z); y = e / (1.f + e); }
    out[idx] = y;
}

// ---------------------------------------------------------------------------
extern "C" void kernel_launch(void* const* d_in, const int* in_sizes, int n_in,
                              void* d_out, int out_size) {
    const float* x  = (const float*)d_in[0];   // (1, 2048, 1024)
    // d_in[1..3] = Wa, Ua, Va : mathematically dead (softmax over size-1 axis)
    const float* Wo = (const float*)d_in[4];   // (28, 28)
    const float* Uo = (const float*)d_in[5];   // (28, 1024)
    const float* Co = (const float*)d_in[6];   // (28, 1024)
    float* out = (float*)d_out;                // (1, 2048, 28)

    void* sPtr = nullptr;
    cudaGetSymbolAddress(&sPtr, g_S);
    cudaMemsetAsync(sPtr, 0, D_HID * sizeof(float));

    kA_computeU<<<T_FRAMES / 8, 128>>>(x, Uo);
    kMeta<<<1, 1024>>>(Co, Wo);
    kD_solve<<<NCHUNK, 32>>>(out);
    kH_satfill<<<(T_FRAMES * V_VOC) / 256, 256>>>(Wo, out);
}

// round 8
// speedup vs baseline: 11.2389x; 1.3181x over previous
#include <cuda_runtime.h>

#define T_FRAMES 2048
#define D_HID    1024
#define V_VOC    28
#define CHUNK    32
#define NCHUNK   (T_FRAMES / CHUNK)

// ---------------------------------------------------------------------------
// Device scratch
// ---------------------------------------------------------------------------
__device__ float g_U[T_FRAMES * V_VOC];   // 0.5*(Uo . x[t-1]); row 0 rewritten by kMeta
__device__ float g_S[D_HID];              // colsum of x (atomic-accumulated; memset to 0)
__device__ float g_CO[V_VOC];             // 0.5*(Co @ S)
__device__ float g_partMn[V_VOC * 256];
__device__ float g_partMx[V_VOC * 256];
__device__ int   g_m;                     // number of active outputs
__device__ int   g_useSerial;
__device__ int   g_halo;                  // 8 or 16
__device__ int   g_actV[32];              // rank -> active v (zero padded)
__device__ float g_B28[32];               // per-v folded bias
__device__ float g_W28[32 * V_VOC];       // per-v 0.25*Wo[v, act[j]] (zero padded)

// ---------------------------------------------------------------------------
// Kernel A: g_U[t+1][v] = 0.5*(Uo[v] . x[t]); fused colsum atomics + min/max.
// x tiles cached in registers (float4), reused across 7 v per warp -> FMA-bound.
// ---------------------------------------------------------------------------
__global__ void __launch_bounds__(128) kA_computeU(const float* __restrict__ x,
                                                   const float* __restrict__ Uo) {
    __shared__ float xs[8][D_HID];
    const int t0 = blockIdx.x * 8;

    const float4* xv = reinterpret_cast<const float4*>(x + (size_t)t0 * D_HID);
    float4* sv = reinterpret_cast<float4*>(&xs[0][0]);
    #pragma unroll
    for (int i = threadIdx.x; i < 8 * D_HID / 4; i += 128)
        sv[i] = xv[i];
    __syncthreads();

    const int warp = threadIdx.x >> 5;
    const int lane = threadIdx.x & 31;

    // fused colsum (conflict-free column sums, spread-address atomics)
    #pragma unroll
    for (int i = 0; i < 8; i++) {
        const int d = threadIdx.x + 128 * i;
        float s = 0.f;
        #pragma unroll
        for (int r = 0; r < 8; r++) s += xs[r][d];
        atomicAdd(&g_S[d], s);
    }

    // register-cached GEMM: acc[vi][r], x chunk reused across the 7 v
    float acc[7][8];
    #pragma unroll
    for (int vi = 0; vi < 7; vi++)
        #pragma unroll
        for (int r = 0; r < 8; r++) acc[vi][r] = 0.f;

    #pragma unroll
    for (int j = 0; j < 8; j++) {
        const int dd = j * 128 + lane * 4;
        float4 xr[8];
        #pragma unroll
        for (int r = 0; r < 8; r++)
            xr[r] = *reinterpret_cast<const float4*>(&xs[r][dd]);
        #pragma unroll
        for (int vi = 0; vi < 7; vi++) {
            const int v = warp * 7 + vi;
            const float4 u4 = __ldg(reinterpret_cast<const float4*>(&Uo[v * D_HID + dd]));
            #pragma unroll
            for (int r = 0; r < 8; r++) {
                float t = fmaf(u4.x, xr[r].x, acc[vi][r]);
                t = fmaf(u4.y, xr[r].y, t);
                t = fmaf(u4.z, xr[r].z, t);
                acc[vi][r] = fmaf(u4.w, xr[r].w, t);
            }
        }
    }

    #pragma unroll
    for (int vi = 0; vi < 7; vi++) {
        const int v = warp * 7 + vi;
        float mn = 1e30f, mx = -1e30f;
        #pragma unroll
        for (int r = 0; r < 8; r++) {
            float s = acc[vi][r];
            #pragma unroll
            for (int o = 16; o; o >>= 1) s += __shfl_xor_sync(0xFFFFFFFFu, s, o);
            const int t = t0 + r + 1;
            if (lane == 0 && t < T_FRAMES) {
                const float uh = 0.5f * s;
                g_U[t * V_VOC + v] = uh;
                mn = fminf(mn, uh);
                mx = fmaxf(mx, uh);
            }
        }
        if (lane == 0) {
            g_partMn[v * 256 + blockIdx.x] = mn;
            g_partMx[v * 256 + blockIdx.x] = mx;
        }
    }
}

// ---------------------------------------------------------------------------
// Kernel Meta: CO + min/max reduce + classify + unified tables (all 28 v).
// ---------------------------------------------------------------------------
__global__ void __launch_bounds__(1024) kMeta(const float* __restrict__ Co,
                                              const float* __restrict__ Wo) {
    const int warp = threadIdx.x >> 5;
    const int lane = threadIdx.x & 31;

    if (warp < V_VOC) {
        float s = 0.f;
        #pragma unroll 4
        for (int j = 0; j < 32; j++) {
            const int d = j * 32 + lane;
            s = fmaf(__ldg(&Co[warp * D_HID + d]), g_S[d], s);
        }
        #pragma unroll
        for (int o = 16; o; o >>= 1) s += __shfl_xor_sync(0xFFFFFFFFu, s, o);
        if (lane == 0) g_CO[warp] = 0.5f * s;

        float mn = 0.f, mx = 0.f;    // include t=0 value 0
        #pragma unroll
        for (int i = 0; i < 8; i++) {
            mn = fminf(mn, g_partMn[warp * 256 + lane + 32 * i]);
            mx = fmaxf(mx, g_partMx[warp * 256 + lane + 32 * i]);
        }
        #pragma unroll
        for (int o = 16; o; o >>= 1) {
            mn = fminf(mn, __shfl_xor_sync(0xFFFFFFFFu, mn, o));
            mx = fmaxf(mx, __shfl_xor_sync(0xFFFFFFFFu, mx, o));
        }
        if (lane == 0) { g_partMn[warp * 256] = mn; g_partMx[warp * 256] = mx; }
    }
    __syncthreads();
    if (warp != 0) return;

    // warp 0: classification + tables. All shuffles uniform.
    const bool valid = lane < V_VOC;
    const int vIdx = valid ? lane : 0;

    float w[V_VOC];
    float rowNeg = 0.f, rowPos = 0.f;
    #pragma unroll
    for (int k = 0; k < V_VOC; k++) {
        w[k] = Wo[vIdx * V_VOC + k];
        rowNeg += fminf(w[k], 0.f);
        rowPos += fmaxf(w[k], 0.f);
    }
    const float coh  = g_CO[vIdx];
    const float sMin = coh + g_partMn[vIdx * 256] + 0.5f * rowNeg;
    const float sMax = coh + g_partMx[vIdx * 256] + 0.5f * rowPos;

    int cls = 2;
    if (sMin > 7.f)  cls = 1;
    if (sMax < -7.f) cls = 0;
    if (!valid)      cls = 0;

    const unsigned amask = __ballot_sync(0xFFFFFFFFu, cls == 2) & 0x0FFFFFFFu;
    const int m = __popc(amask);
    if (lane == 0) g_m = m;

    int clsA[V_VOC];
    #pragma unroll
    for (int k = 0; k < V_VOC; k++)
        clsA[k] = __shfl_sync(0xFFFFFFFFu, cls, k);

    float s1 = 0.f;
    #pragma unroll
    for (int k = 0; k < V_VOC; k++)
        if (clsA[k] == 1) s1 += w[k];

    // active list (identical in every lane)
    int act[V_VOC];
    int cnt = 0;
    #pragma unroll
    for (int k = 0; k < V_VOC; k++)
        if ((amask >> k) & 1u) act[cnt++] = k;

    // unified per-v tables: same folded form for active AND saturated rows
    float sa = 0.f, qrow = 0.f;
    #pragma unroll
    for (int j = 0; j < V_VOC; j++) {
        float wj = 0.f;
        if (j < m) wj = w[act[j]];
        g_W28[lane * V_VOC + j] = 0.25f * wj;
        sa += wj;
        qrow += 0.25f * fabsf(wj);
    }
    g_B28[lane] = coh + 0.5f * s1 + 0.25f * sa;
    g_actV[lane] = (lane < m) ? act[lane] : 0;

    if (cls != 2) qrow = 0.f;          // contraction over the active subsystem only
    #pragma unroll
    for (int o = 16; o; o >>= 1)
        qrow = fmaxf(qrow, __shfl_xor_sync(0xFFFFFFFFu, qrow, o));
    if (lane == 0) {
        g_useSerial = (m > 16 || qrow > 0.40f) ? 1 : 0;
        const float q = fmaxf(qrow, 1e-4f);
        g_halo = (9.f * __logf(q) < -16.2f) ? 8 : 16;
    }

    // t=0 exactness under folded-bias form: Uh0 = -0.5*s1
    if (valid) g_U[lane] = -0.5f * s1;
}

// ---------------------------------------------------------------------------
// One unified recurrence step (indexed shuffles from the active lanes)
// ---------------------------------------------------------------------------
template <int M, int NACC>
__device__ __forceinline__ float stepFn(const float* __restrict__ w,
                                        const int* __restrict__ src,
                                        float th, float bias) {
    float thc[M];
    #pragma unroll
    for (int c = 0; c < M; c++)
        thc[c] = __shfl_sync(0xFFFFFFFFu, th, src[c]);
    float a[NACC];
    a[0] = bias;
    #pragma unroll
    for (int q = 1; q < NACC; q++) a[q] = 0.f;
    #pragma unroll
    for (int c = 0; c < M; c++)
        a[c % NACC] = fmaf(w[c], thc[c], a[c % NACC]);
    float s = a[0];
    if (NACC == 2) s = a[0] + a[1];
    if (NACC == 4) s = (a[0] + a[1]) + (a[2] + a[3]);
    float nth;
    asm("tanh.approx.f32 %0, %1;" : "=f"(nth) : "f"(s));
    return nth;
}

// ---------------------------------------------------------------------------
// Chunked solver: every lane owns one v (active or saturated); all 28
// outputs written directly. Warm-up halo from the decoupled guess.
// ---------------------------------------------------------------------------
template <int M, int NACC>
__device__ __forceinline__ void chunkBody(float* __restrict__ out) {
    const int lane = threadIdx.x;
    const int v = (lane < V_VOC) ? lane : (V_VOC - 1);
    const bool writer = (lane < V_VOC);

    const float B = g_B28[v];
    float w[M];
    int src[M];
    #pragma unroll
    for (int c = 0; c < M; c++) {
        w[c]   = g_W28[v * V_VOC + c];
        src[c] = g_actV[c];
    }

    const int halo = g_halo;
    const int t0 = blockIdx.x * CHUNK;
    const int ts = (blockIdx.x == 0) ? 0 : (t0 - halo);
    const int te = t0 + CHUNK;

    float th;
    if (blockIdx.x == 0) {
        th = -1.f;                                 // y_prev = 0 exactly
    } else {
        const float s0 = B + __ldg(&g_U[(ts - 1) * V_VOC + v]);
        asm("tanh.approx.f32 %0, %1;" : "=f"(th) : "f"(s0));
    }

    float ub[8];
    #pragma unroll
    for (int i = 0; i < 8; i++) ub[i] = __ldg(&g_U[(ts + i) * V_VOC + v]);

    for (int t = ts; t < te; t += 8) {
        #pragma unroll
        for (int i = 0; i < 8; i++) {
            const float bias = B + ub[i];
            const int tn = t + i + 8;
            if (tn < te) ub[i] = __ldg(&g_U[tn * V_VOC + v]);
            th = stepFn<M, NACC>(w, src, th, bias);
            if (writer && (t + i) >= t0)
                out[(t + i) * V_VOC + v] = fmaf(0.5f, th, 0.5f);
        }
    }
}

// Full-serial fallback (block 0 only), same unified scheme
__device__ __forceinline__ void serialBody(float* __restrict__ out) {
    const int lane = threadIdx.x;
    const int v = (lane < V_VOC) ? lane : (V_VOC - 1);
    const bool writer = (lane < V_VOC);

    const float B = g_B28[v];
    float w[V_VOC];
    int src[V_VOC];
    #pragma unroll
    for (int c = 0; c < V_VOC; c++) {
        w[c]   = g_W28[v * V_VOC + c];
        src[c] = g_actV[c];
    }

    float ub[8];
    #pragma unroll
    for (int i = 0; i < 8; i++) ub[i] = g_U[i * V_VOC + v];

    float th = -1.0f;
    for (int t = 0; t < T_FRAMES; t += 8) {
        #pragma unroll
        for (int i = 0; i < 8; i++) {
            const float bias = B + ub[i];
            const int tn = t + i + 8;
            if (tn < T_FRAMES) ub[i] = __ldg(&g_U[tn * V_VOC + v]);
            th = stepFn<V_VOC, 4>(w, src, th, bias);
            if (writer) out[(t + i) * V_VOC + v] = fmaf(0.5f, th, 0.5f);
        }
    }
}

__global__ void __launch_bounds__(32) kD_solve(float* __restrict__ out) {
    if (g_useSerial) {
        if (blockIdx.x != 0) return;
        serialBody(out);
        return;
    }
    const int m = g_m;
    if      (m <= 4) chunkBody<4, 2>(out);
    else if (m <= 8) chunkBody<8, 4>(out);
    else             chunkBody<16, 4>(out);
}

// ---------------------------------------------------------------------------
extern "C" void kernel_launch(void* const* d_in, const int* in_sizes, int n_in,
                              void* d_out, int out_size) {
    const float* x  = (const float*)d_in[0];   // (1, 2048, 1024)
    // d_in[1..3] = Wa, Ua, Va : mathematically dead (softmax over size-1 axis)
    const float* Wo = (const float*)d_in[4];   // (28, 28)
    const float* Co = (const float*)d_in[6];   // (28, 1024)
    const float* Uo = (const float*)d_in[5];   // (28, 1024)
    float* out = (float*)d_out;                // (1, 2048, 28)

    void* sPtr = nullptr;
    cudaGetSymbolAddress(&sPtr, g_S);
    cudaMemsetAsync(sPtr, 0, D_HID * sizeof(float));

    kA_computeU<<<T_FRAMES / 8, 128>>>(x, Uo);
    kMeta<<<1, 1024>>>(Co, Wo);
    kD_solve<<<NCHUNK, 32>>>(out);
}

// round 9
// speedup vs baseline: 11.4730x; 1.0208x over previous
#include <cuda_runtime.h>

#define T_FRAMES 2048
#define D_HID    1024
#define V_VOC    28
#define ROWS     4
#define NBLK_A   (T_FRAMES / ROWS)      // 512
#define CHUNK    16
#define NCHUNK   (T_FRAMES / CHUNK)     // 128

// ---------------------------------------------------------------------------
// Device scratch
// ---------------------------------------------------------------------------
__device__ float g_U[T_FRAMES * V_VOC];   // 0.5*(Uo . x[t-1]); row 0 rewritten by kMeta
__device__ float g_S[D_HID];              // colsum of x (atomic-accumulated; memset to 0)
__device__ float g_CO[V_VOC];             // 0.5*(Co @ S)
__device__ float g_partMn[V_VOC * NBLK_A];
__device__ float g_partMx[V_VOC * NBLK_A];
__device__ int   g_m;                     // number of active outputs
__device__ int   g_useSerial;
__device__ int   g_halo;                  // 8 or 16
__device__ int   g_actV[32];              // rank -> active v (zero padded)
__device__ float g_B28[32];               // per-v folded bias
__device__ float g_W28[32 * V_VOC];       // per-v 0.25*Wo[v, act[j]] (zero padded)

// ---------------------------------------------------------------------------
// Kernel A: g_U[t+1][v] = 0.5*(Uo[v] . x[t]); fused colsum atomics + min/max.
// 4 t-rows per block (512 blocks) for high occupancy; x tile cached in regs.
// ---------------------------------------------------------------------------
__global__ void __launch_bounds__(128) kA_computeU(const float* __restrict__ x,
                                                   const float* __restrict__ Uo) {
    __shared__ float xs[ROWS][D_HID];              // 16 KB
    const int t0 = blockIdx.x * ROWS;

    const float4* xv = reinterpret_cast<const float4*>(x + (size_t)t0 * D_HID);
    float4* sv = reinterpret_cast<float4*>(&xs[0][0]);
    #pragma unroll
    for (int i = 0; i < ROWS * D_HID / 4 / 128; i++)
        sv[threadIdx.x + 128 * i] = xv[threadIdx.x + 128 * i];
    __syncthreads();

    const int warp = threadIdx.x >> 5;
    const int lane = threadIdx.x & 31;

    // fused colsum (conflict-free column sums, spread-address atomics)
    #pragma unroll
    for (int i = 0; i < 8; i++) {
        const int d = threadIdx.x + 128 * i;
        float s = 0.f;
        #pragma unroll
        for (int r = 0; r < ROWS; r++) s += xs[r][d];
        atomicAdd(&g_S[d], s);
    }

    // register GEMM: acc[vi][r]; x chunk reused across the 7 v of this warp
    float acc[7][ROWS];
    #pragma unroll
    for (int vi = 0; vi < 7; vi++)
        #pragma unroll
        for (int r = 0; r < ROWS; r++) acc[vi][r] = 0.f;

    #pragma unroll
    for (int j = 0; j < 8; j++) {
        const int dd = j * 128 + lane * 4;
        float4 xr[ROWS];
        #pragma unroll
        for (int r = 0; r < ROWS; r++)
            xr[r] = *reinterpret_cast<const float4*>(&xs[r][dd]);
        #pragma unroll
        for (int vi = 0; vi < 7; vi++) {
            const int v = warp * 7 + vi;
            const float4 u4 = __ldg(reinterpret_cast<const float4*>(&Uo[v * D_HID + dd]));
            #pragma unroll
            for (int r = 0; r < ROWS; r++) {
                float t = fmaf(u4.x, xr[r].x, acc[vi][r]);
                t = fmaf(u4.y, xr[r].y, t);
                t = fmaf(u4.z, xr[r].z, t);
                acc[vi][r] = fmaf(u4.w, xr[r].w, t);
            }
        }
    }

    #pragma unroll
    for (int vi = 0; vi < 7; vi++) {
        const int v = warp * 7 + vi;
        float mn = 1e30f, mx = -1e30f;
        #pragma unroll
        for (int r = 0; r < ROWS; r++) {
            float s = acc[vi][r];
            #pragma unroll
            for (int o = 16; o; o >>= 1) s += __shfl_xor_sync(0xFFFFFFFFu, s, o);
            const int t = t0 + r + 1;
            if (lane == 0 && t < T_FRAMES) {
                const float uh = 0.5f * s;
                g_U[t * V_VOC + v] = uh;
                mn = fminf(mn, uh);
                mx = fmaxf(mx, uh);
            }
        }
        if (lane == 0) {
            g_partMn[v * NBLK_A + blockIdx.x] = mn;
            g_partMx[v * NBLK_A + blockIdx.x] = mx;
        }
    }
}

// ---------------------------------------------------------------------------
// Kernel Meta: CO + min/max reduce + classify + unified tables (all 28 v).
// ---------------------------------------------------------------------------
__global__ void __launch_bounds__(1024) kMeta(const float* __restrict__ Co,
                                              const float* __restrict__ Wo) {
    const int warp = threadIdx.x >> 5;
    const int lane = threadIdx.x & 31;

    if (warp < V_VOC) {
        float s = 0.f;
        #pragma unroll 4
        for (int j = 0; j < 32; j++) {
            const int d = j * 32 + lane;
            s = fmaf(__ldg(&Co[warp * D_HID + d]), g_S[d], s);
        }
        #pragma unroll
        for (int o = 16; o; o >>= 1) s += __shfl_xor_sync(0xFFFFFFFFu, s, o);
        if (lane == 0) g_CO[warp] = 0.5f * s;

        float mn = 0.f, mx = 0.f;    // include t=0 value 0
        #pragma unroll
        for (int i = 0; i < NBLK_A / 32; i++) {
            mn = fminf(mn, g_partMn[warp * NBLK_A + lane + 32 * i]);
            mx = fmaxf(mx, g_partMx[warp * NBLK_A + lane + 32 * i]);
        }
        #pragma unroll
        for (int o = 16; o; o >>= 1) {
            mn = fminf(mn, __shfl_xor_sync(0xFFFFFFFFu, mn, o));
            mx = fmaxf(mx, __shfl_xor_sync(0xFFFFFFFFu, mx, o));
        }
        if (lane == 0) { g_partMn[warp * NBLK_A] = mn; g_partMx[warp * NBLK_A] = mx; }
    }
    __syncthreads();
    if (warp != 0) return;

    // warp 0: classification + tables. All shuffles uniform.
    const bool valid = lane < V_VOC;
    const int vIdx = valid ? lane : 0;

    float w[V_VOC];
    float rowNeg = 0.f, rowPos = 0.f;
    #pragma unroll
    for (int k = 0; k < V_VOC; k++) {
        w[k] = Wo[vIdx * V_VOC + k];
        rowNeg += fminf(w[k], 0.f);
        rowPos += fmaxf(w[k], 0.f);
    }
    const float coh  = g_CO[vIdx];
    const float sMin = coh + g_partMn[vIdx * NBLK_A] + 0.5f * rowNeg;
    const float sMax = coh + g_partMx[vIdx * NBLK_A] + 0.5f * rowPos;

    int cls = 2;
    if (sMin > 7.f)  cls = 1;
    if (sMax < -7.f) cls = 0;
    if (!valid)      cls = 0;

    const unsigned amask = __ballot_sync(0xFFFFFFFFu, cls == 2) & 0x0FFFFFFFu;
    const int m = __popc(amask);
    if (lane == 0) g_m = m;

    int clsA[V_VOC];
    #pragma unroll
    for (int k = 0; k < V_VOC; k++)
        clsA[k] = __shfl_sync(0xFFFFFFFFu, cls, k);

    float s1 = 0.f;
    #pragma unroll
    for (int k = 0; k < V_VOC; k++)
        if (clsA[k] == 1) s1 += w[k];

    int act[V_VOC];
    int cnt = 0;
    #pragma unroll
    for (int k = 0; k < V_VOC; k++)
        if ((amask >> k) & 1u) act[cnt++] = k;

    // unified per-v tables: same folded form for active AND saturated rows
    float sa = 0.f, qrow = 0.f;
    #pragma unroll
    for (int j = 0; j < V_VOC; j++) {
        float wj = 0.f;
        if (j < m) wj = w[act[j]];
        g_W28[lane * V_VOC + j] = 0.25f * wj;
        sa += wj;
        qrow += 0.25f * fabsf(wj);
    }
    g_B28[lane] = coh + 0.5f * s1 + 0.25f * sa;
    g_actV[lane] = (lane < m) ? act[lane] : 0;

    if (cls != 2) qrow = 0.f;          // contraction over the active subsystem only
    #pragma unroll
    for (int o = 16; o; o >>= 1)
        qrow = fmaxf(qrow, __shfl_xor_sync(0xFFFFFFFFu, qrow, o));
    if (lane == 0) {
        g_useSerial = (m > 16 || qrow > 0.40f) ? 1 : 0;
        const float q = fmaxf(qrow, 1e-4f);
        g_halo = (9.f * __logf(q) < -16.2f) ? 8 : 16;
    }

    // t=0 exactness under folded-bias form: Uh0 = -0.5*s1
    if (valid) g_U[lane] = -0.5f * s1;
}

// ---------------------------------------------------------------------------
// One unified recurrence step (indexed shuffles from the active lanes)
// ---------------------------------------------------------------------------
template <int M, int NACC>
__device__ __forceinline__ float stepFn(const float* __restrict__ w,
                                        const int* __restrict__ src,
                                        float th, float bias) {
    float thc[M];
    #pragma unroll
    for (int c = 0; c < M; c++)
        thc[c] = __shfl_sync(0xFFFFFFFFu, th, src[c]);
    float a[NACC];
    a[0] = bias;
    #pragma unroll
    for (int q = 1; q < NACC; q++) a[q] = 0.f;
    #pragma unroll
    for (int c = 0; c < M; c++)
        a[c % NACC] = fmaf(w[c], thc[c], a[c % NACC]);
    float s = a[0];
    if (NACC == 2) s = a[0] + a[1];
    if (NACC == 4) s = (a[0] + a[1]) + (a[2] + a[3]);
    float nth;
    asm("tanh.approx.f32 %0, %1;" : "=f"(nth) : "f"(s));
    return nth;
}

// ---------------------------------------------------------------------------
// Chunked solver: every lane owns one v; warm-up halo from decoupled guess.
// ---------------------------------------------------------------------------
template <int M, int NACC>
__device__ __forceinline__ void chunkBody(float* __restrict__ out) {
    const int lane = threadIdx.x;
    const int v = (lane < V_VOC) ? lane : (V_VOC - 1);
    const bool writer = (lane < V_VOC);

    const float B = g_B28[v];
    float w[M];
    int src[M];
    #pragma unroll
    for (int c = 0; c < M; c++) {
        w[c]   = g_W28[v * V_VOC + c];
        src[c] = g_actV[c];
    }

    const int halo = g_halo;
    const int t0 = blockIdx.x * CHUNK;
    const int ts = (blockIdx.x == 0) ? 0 : (t0 - halo);
    const int te = t0 + CHUNK;

    float th;
    if (blockIdx.x == 0) {
        th = -1.f;                                 // y_prev = 0 exactly
    } else {
        const float s0 = B + __ldg(&g_U[(ts - 1) * V_VOC + v]);
        asm("tanh.approx.f32 %0, %1;" : "=f"(th) : "f"(s0));
    }

    float ub[8];
    #pragma unroll
    for (int i = 0; i < 8; i++) ub[i] = __ldg(&g_U[(ts + i) * V_VOC + v]);

    for (int t = ts; t < te; t += 8) {
        #pragma unroll
        for (int i = 0; i < 8; i++) {
            const float bias = B + ub[i];
            const int tn = t + i + 8;
            if (tn < te) ub[i] = __ldg(&g_U[tn * V_VOC + v]);
            th = stepFn<M, NACC>(w, src, th, bias);
            if (writer && (t + i) >= t0)
                out[(t + i) * V_VOC + v] = fmaf(0.5f, th, 0.5f);
        }
    }
}

// Full-serial fallback (block 0 only), same unified scheme
__device__ __forceinline__ void serialBody(float* __restrict__ out) {
    const int lane = threadIdx.x;
    const int v = (lane < V_VOC) ? lane : (V_VOC - 1);
    const bool writer = (lane < V_VOC);

    const float B = g_B28[v];
    float w[V_VOC];
    int src[V_VOC];
    #pragma unroll
    for (int c = 0; c < V_VOC; c++) {
        w[c]   = g_W28[v * V_VOC + c];
        src[c] = g_actV[c];
    }

    float ub[8];
    #pragma unroll
    for (int i = 0; i < 8; i++) ub[i] = g_U[i * V_VOC + v];

    float th = -1.0f;
    for (int t = 0; t < T_FRAMES; t += 8) {
        #pragma unroll
        for (int i = 0; i < 8; i++) {
            const float bias = B + ub[i];
            const int tn = t + i + 8;
            if (tn < T_FRAMES) ub[i] = __ldg(&g_U[tn * V_VOC + v]);
            th = stepFn<V_VOC, 4>(w, src, th, bias);
            if (writer) out[(t + i) * V_VOC + v] = fmaf(0.5f, th, 0.5f);
        }
    }
}

__global__ void __launch_bounds__(32) kD_solve(float* __restrict__ out) {
    if (g_useSerial) {
        if (blockIdx.x != 0) return;
        serialBody(out);
        return;
    }
    const int m = g_m;
    if      (m <= 4) chunkBody<4, 2>(out);
    else if (m <= 8) chunkBody<8, 4>(out);
    else             chunkBody<16, 4>(out);
}

// ---------------------------------------------------------------------------
extern "C" void kernel_launch(void* const* d_in, const int* in_sizes, int n_in,
                              void* d_out, int out_size) {
    const float* x  = (const float*)d_in[0];   // (1, 2048, 1024)
    // d_in[1..3] = Wa, Ua, Va : mathematically dead (softmax over size-1 axis)
    const float* Wo = (const float*)d_in[4];   // (28, 28)
    const float* Uo = (const float*)d_in[5];   // (28, 1024)
    const float* Co = (const float*)d_in[6];   // (28, 1024)
    float* out = (float*)d_out;                // (1, 2048, 28)

    void* sPtr = nullptr;
    cudaGetSymbolAddress(&sPtr, g_S);
    cudaMemsetAsync(sPtr, 0, D_HID * sizeof(float));

    kA_computeU<<<NBLK_A, 128>>>(x, Uo);
    kMeta<<<1, 1024>>>(Co, Wo);
    kD_solve<<<NCHUNK, 32>>>(out);
}